// round 12
// baseline (speedup 1.0000x reference)
#include <cuda_runtime.h>
#include <cuda_bf16.h>
#include <math.h>
#include <stdint.h>

// Problem constants
#define Bz 8
#define Nn 1024
#define Dd 256
#define Hh 8
#define HC 4
#define DH 64
#define HD 2048                 // Hh*Dd
#define ND (Nn*Dd)              // 262144
#define NNt ((size_t)Nn*Nn)     // 1048576

// ---------------- scratch (device globals) ----------------
__device__ float g_posq[Bz*Dd];
__device__ float g_pqpart[Bz*16*Dd];
__device__ float g_pqcnt[Bz*16];
__device__ float g_qs[Bz*Dd];
__device__ float g_w[Bz*Dd];
__device__ float g_sel[Bz*Nn];
__device__ uint8_t g_connect[(size_t)Bz*Nn*Nn];
__device__ float g_s1[Bz*Hh*Nn];
__device__ float g_s2[Bz*Hh*Nn];
__device__ float g_so1[Bz*Nn];
__device__ float g_so2[Bz*Nn];
__device__ __nv_bfloat16 g_attn_bf[(size_t)Bz*Hh*Nn*Nn];   // GAT probs
__device__ __nv_bfloat16 g_attno_bf[(size_t)Bz*Nn*Nn];

__device__ __nv_bfloat16 g_x2[2*(size_t)Bz*ND];
__device__ __nv_bfloat16 g_fa2[2*(size_t)Bz*ND];
__device__ __nv_bfloat16 g_Wh2[2*(size_t)Bz*Hh*ND];
__device__ __nv_bfloat16 g_WhT2[2*(size_t)Bz*Hh*ND];
__device__ __nv_bfloat16 g_cat2[2*(size_t)Bz*Nn*HD];
__device__ __nv_bfloat16 g_Who2[2*(size_t)Bz*ND];
__device__ __nv_bfloat16 g_WhoT2[2*(size_t)Bz*ND];
__device__ __nv_bfloat16 g_gout2[2*(size_t)Bz*ND];
__device__ __nv_bfloat16 g_qx2[2*(size_t)Bz*ND];
__device__ __nv_bfloat16 g_kv2[2*(size_t)Bz*ND];
__device__ __nv_bfloat16 g_q2[2*(size_t)Bz*ND];
__device__ __nv_bfloat16 g_k2[2*(size_t)Bz*ND];
__device__ __nv_bfloat16 g_vT2[2*(size_t)Bz*ND];
__device__ __nv_bfloat16 g_o2[2*(size_t)Bz*ND];
// transposed weights (planes)
__device__ __nv_bfloat16 g_adjWT2[2*Dd*Dd];
__device__ __nv_bfloat16 g_gatWT2[2*Hh*Dd*Dd];
__device__ __nv_bfloat16 g_WoT2[2*HD*Dd];
__device__ __nv_bfloat16 g_caWqT2[2*Dd*Dd];
__device__ __nv_bfloat16 g_caWkT2[2*Dd*Dd];
__device__ __nv_bfloat16 g_caWvT2[2*Dd*Dd];
__device__ __nv_bfloat16 g_caWpT2[2*Dd*Dd];

// ---------------- streams/events ----------------
struct HXStreams {
    cudaStream_t s1, s2;
    cudaEvent_t e0, eT, eX, eConn, eQ, eKV, eK;
    HXStreams() {
        cudaStreamCreateWithFlags(&s1, cudaStreamNonBlocking);
        cudaStreamCreateWithFlags(&s2, cudaStreamNonBlocking);
        cudaEventCreateWithFlags(&e0, cudaEventDisableTiming);
        cudaEventCreateWithFlags(&eT, cudaEventDisableTiming);
        cudaEventCreateWithFlags(&eX, cudaEventDisableTiming);
        cudaEventCreateWithFlags(&eConn, cudaEventDisableTiming);
        cudaEventCreateWithFlags(&eQ, cudaEventDisableTiming);
        cudaEventCreateWithFlags(&eKV, cudaEventDisableTiming);
        cudaEventCreateWithFlags(&eK, cudaEventDisableTiming);
    }
};
static HXStreams hx;

// ---------------- low-level helpers ----------------
__device__ __forceinline__ uint32_t smem_u32(const void* p) {
    uint32_t a;
    asm("{ .reg .u64 t; cvta.to.shared.u64 t, %1; cvt.u32.u64 %0, t; }" : "=r"(a) : "l"(p));
    return a;
}
__device__ __forceinline__ void ldsm4(uint32_t* r, uint32_t addr) {
    asm volatile("ldmatrix.sync.aligned.m8n8.x4.shared.b16 {%0,%1,%2,%3}, [%4];"
        : "=r"(r[0]), "=r"(r[1]), "=r"(r[2]), "=r"(r[3]) : "r"(addr));
}
__device__ __forceinline__ void mma16816(float* c, const uint32_t* a, const uint32_t* b) {
    asm volatile("mma.sync.aligned.m16n8k16.row.col.f32.bf16.bf16.f32 "
        "{%0,%1,%2,%3}, {%4,%5,%6,%7}, {%8,%9}, {%0,%1,%2,%3};"
        : "+f"(c[0]), "+f"(c[1]), "+f"(c[2]), "+f"(c[3])
        : "r"(a[0]), "r"(a[1]), "r"(a[2]), "r"(a[3]), "r"(b[0]), "r"(b[1]));
}
__device__ __forceinline__ void split1(float v, __nv_bfloat16& h, __nv_bfloat16& l) {
    h = __float2bfloat16(v);
    l = __float2bfloat16(v - __bfloat162float(h));
}
__device__ __forceinline__ uint32_t pack2(__nv_bfloat16 a, __nv_bfloat16 b) {
    return (uint32_t)__bfloat16_as_ushort(a) | ((uint32_t)__bfloat16_as_ushort(b) << 16);
}
__device__ __forceinline__ uint32_t packf2(float a, float b) {
    uint32_t r;
    asm("cvt.rn.bf16x2.f32 %0, %1, %2;" : "=r"(r) : "f"(b), "f"(a));
    return r;
}
#define CP16(dst, src) \
    asm volatile("cp.async.cg.shared.global [%0], [%1], 16;" :: "r"(dst), "l"(src))
#define CP_COMMIT() asm volatile("cp.async.commit_group;" ::: "memory")

template <bool MAX>
__device__ __forceinline__ float bred(float v, float* r8, int wid, int lane) {
    #pragma unroll
    for (int o = 16; o; o >>= 1) {
        float u = __shfl_xor_sync(0xffffffffu, v, o);
        v = MAX ? fmaxf(v, u) : (v + u);
    }
    if (lane == 0) r8[wid] = v;
    __syncthreads();
    if (wid == 0) {
        float u = r8[lane & 7];
        #pragma unroll
        for (int o = 4; o; o >>= 1) {
            float t = __shfl_xor_sync(0xffffffffu, u, o);
            u = MAX ? fmaxf(u, t) : (u + t);
        }
        if (lane == 0) r8[0] = u;
    }
    __syncthreads();
    return r8[0];
}

// ---------------- split x into planes ----------------
__global__ void k_split(const float* __restrict__ in, __nv_bfloat16* __restrict__ outp, long plane)
{
    int i = blockIdx.x * 256 + threadIdx.x;
    float4 v = reinterpret_cast<const float4*>(in)[i];
    __nv_bfloat16 h0, l0, h1, l1, h2, l2, h3, l3;
    split1(v.x, h0, l0); split1(v.y, h1, l1); split1(v.z, h2, l2); split1(v.w, h3, l3);
    reinterpret_cast<uint2*>(outp)[i] = make_uint2(pack2(h0, h1), pack2(h2, h3));
    reinterpret_cast<uint2*>(outp + plane)[i] = make_uint2(pack2(l0, l1), pack2(l2, l3));
}

// ---------------- merged transpose kernel ----------------
__global__ void k_transpose_all(const float* adjW, __nv_bfloat16* adjWT,
                                const float* caWq, __nv_bfloat16* caWqT,
                                const float* caWk, __nv_bfloat16* caWkT,
                                const float* caWv, __nv_bfloat16* caWvT,
                                const float* caWp, __nv_bfloat16* caWpT,
                                const float* gatW, __nv_bfloat16* gatWT,
                                const float* gatWo, __nv_bfloat16* WoT)
{
    __shared__ float t[32][33];
    int id = blockIdx.x;
    int tx = threadIdx.x, ty = threadIdx.y;
    const float* src; __nv_bfloat16* dh; long plane; int R, C, bx, by;
    if (id < 320) {
        const float* srcs[5] = {adjW, caWq, caWk, caWv, caWp};
        __nv_bfloat16* dsts[5] = {adjWT, caWqT, caWkT, caWvT, caWpT};
        int m = id >> 6, l = id & 63;
        src = srcs[m]; dh = dsts[m]; plane = Dd * Dd;
        R = Dd; C = Dd; bx = (l & 7) * 32; by = (l >> 3) * 32;
    } else if (id < 832) {
        int l = id - 320; int z = l >> 6; l &= 63;
        src = gatW + (size_t)z * Dd * Dd; dh = gatWT + (size_t)z * Dd * Dd;
        plane = (long)Hh * Dd * Dd;
        R = Dd; C = Dd; bx = (l & 7) * 32; by = (l >> 3) * 32;
    } else {
        int l = id - 832;
        src = gatWo; dh = WoT; plane = (long)HD * Dd;
        R = HD; C = Dd; bx = (l & 7) * 32; by = (l >> 3) * 32;
    }
    #pragma unroll
    for (int i = 0; i < 32; i += 8)
        t[ty + i][tx] = src[(size_t)(by + ty + i) * C + bx + tx];
    __syncthreads();
    #pragma unroll
    for (int i = 0; i < 32; i += 8) {
        float v = t[tx][ty + i];
        __nv_bfloat16 h, l2;
        split1(v, h, l2);
        size_t o = (size_t)(bx + ty + i) * R + by + tx;
        dh[o] = h; dh[plane + o] = l2;
    }
}

// ---------------- plane-pair bf16 mma.sync NT GEMM ----------------
// BM = WM * MF * 16. Warp tile = (MF*16) x 32.
enum { EPI_NONE = 0, EPI_ELU = 1, EPI_CONNECT = 2, EPI_RESID = 3 };
enum { OUT_F32 = 0, OUT_PLANES = 1, OUT_CONNECT = 2, OUT_NONE = 3 };
#define ROWB 80

template <int MF, int BN, int WM, int WN, int EPI, int NA, int OUT, bool DUAL, int ST>
__global__ void __launch_bounds__(256, 2)
mma_gemm(const __nv_bfloat16* __restrict__ A, long aPlane,
         const __nv_bfloat16* __restrict__ Bm, long bPlane,
         void* __restrict__ Cv, long cPlane,
         int K, int lda, int ldb, int ldc, int zInner,
         long sAb, long sAi, long sBb, long sBi, long sCb, long sCi,
         const float* __restrict__ e1, long sE1b, const float* __restrict__ e2,
         __nv_bfloat16* __restrict__ Ct, long ctPlane, long sCtb, long sCti, int ldct)
{
    constexpr int BM = WM * MF * 16;
    constexpr int ABYTES = BM * ROWB;
    constexpr int BBYTES = BN * ROWB;
    constexpr int STR = BM + 8;
    constexpr int STGPL = BN * STR;

    extern __shared__ char smem[];
    const uint32_t sb = smem_u32(smem);

    const int tid = threadIdx.x;
    const int wid = tid >> 5;
    const int lane = tid & 31;

    const int z = blockIdx.z;
    const int zb = z / zInner, zi = z % zInner;
    const __nv_bfloat16* Ap = A + (size_t)zb * sAb + (size_t)zi * sAi;
    const __nv_bfloat16* Bp = Bm + (size_t)zb * sBb + (size_t)zi * sBi;
    float* Cpf = (float*)Cv + (size_t)zb * sCb + (size_t)zi * sCi;
    __nv_bfloat16* Cpb = (__nv_bfloat16*)Cv + (size_t)zb * sCb + (size_t)zi * sCi;
    uint8_t* Cp8 = (uint8_t*)Cv + (size_t)zb * sCb + (size_t)zi * sCi;
    const float* e1p = e1 ? (e1 + (size_t)zb * sE1b) : nullptr;

    const int m0 = blockIdx.y * BM;
    const int n0 = blockIdx.x * BN;

    const int crow = tid >> 2;
    const int cch = tid & 3;

    const int wid_m = wid % WM;
    const int wid_n = wid / WM;
    const int g = lane >> 3, rl = lane & 7;
    const int aRowBase = wid_m * (MF * 16) + (g & 1) * 8 + rl;
    const int aKsel = (g >> 1) * 8;
    const int bRowBase = wid_n * 32 + (g >> 1) * 8 + rl;
    const int bKsel = (g & 1) * 8;

    float acc[MF][4][4] = {};
    const int nkt = K >> 5;
    const uint32_t bbase = ST * NA * ABYTES;

    auto copyTile = [&](int kk, int stage) {
        #pragma unroll
        for (int pl = 0; pl < NA; pl++) {
            const __nv_bfloat16* src = Ap + (size_t)pl * aPlane;
            uint32_t dst0 = sb + (stage * NA + pl) * ABYTES;
            #pragma unroll
            for (int i = 0; i < BM / 64; i++) {
                int row = crow + 64 * i;
                CP16(dst0 + row * ROWB + cch * 16,
                     src + (size_t)(m0 + row) * lda + kk + cch * 8);
            }
        }
        #pragma unroll
        for (int pl = 0; pl < 2; pl++) {
            const __nv_bfloat16* src = Bp + (size_t)pl * bPlane;
            uint32_t dst0 = sb + bbase + (stage * 2 + pl) * BBYTES;
            #pragma unroll
            for (int i = 0; i < BN / 64; i++) {
                int row = crow + 64 * i;
                CP16(dst0 + row * ROWB + cch * 16,
                     src + (size_t)(n0 + row) * ldb + kk + cch * 8);
            }
        }
    };

    copyTile(0, 0); CP_COMMIT();

    for (int kt = 0; kt < nkt; kt++) {
        const int stage = kt & 1;
        const bool more = (kt + 1 < nkt);
        if (more) { copyTile((kt + 1) << 5, (kt + 1) & 1); CP_COMMIT(); }
        if (more) asm volatile("cp.async.wait_group 1;" ::: "memory");
        else      asm volatile("cp.async.wait_group 0;" ::: "memory");
        __syncthreads();

        const uint32_t sAhi = sb + stage * NA * ABYTES;
        const uint32_t sAlo = sAhi + ABYTES;
        const uint32_t sBhi = sb + bbase + stage * 2 * BBYTES;
        const uint32_t sBlo = sBhi + BBYTES;

        #pragma unroll
        for (int j = 0; j < 2; j++) {
            const int kb = j * 16;
            uint32_t a[MF][4], bh[4][2], bl[4][2];
            #pragma unroll
            for (int im = 0; im < MF; im++)
                ldsm4(a[im], sAhi + (uint32_t)((aRowBase + im * 16) * ROWB + (kb + aKsel) * 2));
            #pragma unroll
            for (int i2 = 0; i2 < 2; i2++) {
                uint32_t t[4];
                ldsm4(t, sBhi + (uint32_t)((bRowBase + i2 * 16) * ROWB + (kb + bKsel) * 2));
                bh[2 * i2][0] = t[0]; bh[2 * i2][1] = t[1];
                bh[2 * i2 + 1][0] = t[2]; bh[2 * i2 + 1][1] = t[3];
            }
            #pragma unroll
            for (int im = 0; im < MF; im++)
                #pragma unroll
                for (int in = 0; in < 4; in++)
                    mma16816(acc[im][in], a[im], bh[in]);
            #pragma unroll
            for (int i2 = 0; i2 < 2; i2++) {
                uint32_t t[4];
                ldsm4(t, sBlo + (uint32_t)((bRowBase + i2 * 16) * ROWB + (kb + bKsel) * 2));
                bl[2 * i2][0] = t[0]; bl[2 * i2][1] = t[1];
                bl[2 * i2 + 1][0] = t[2]; bl[2 * i2 + 1][1] = t[3];
            }
            #pragma unroll
            for (int im = 0; im < MF; im++)
                #pragma unroll
                for (int in = 0; in < 4; in++)
                    mma16816(acc[im][in], a[im], bl[in]);
            if (NA == 2) {
                #pragma unroll
                for (int im = 0; im < MF; im++)
                    ldsm4(a[im], sAlo + (uint32_t)((aRowBase + im * 16) * ROWB + (kb + aKsel) * 2));
                #pragma unroll
                for (int im = 0; im < MF; im++)
                    #pragma unroll
                    for (int in = 0; in < 4; in++)
                        mma16816(acc[im][in], a[im], bh[in]);
            }
        }
        __syncthreads();
    }

    // epilogue
    __nv_bfloat16* stg = reinterpret_cast<__nv_bfloat16*>(smem);
    const int mw = m0 + wid_m * (MF * 16);
    const int nw = n0 + wid_n * 32;
    #pragma unroll
    for (int im = 0; im < MF; im++) {
        const int row = mw + im * 16 + (lane >> 2);
        const float sr0 = (EPI == EPI_CONNECT) ? e1p[row] : 0.f;
        const float sr1 = (EPI == EPI_CONNECT) ? e1p[row + 8] : 0.f;
        #pragma unroll
        for (int in = 0; in < 4; in++) {
            const int col = nw + in * 8 + (lane & 3) * 2;
            float v00 = acc[im][in][0], v01 = acc[im][in][1];
            float v10 = acc[im][in][2], v11 = acc[im][in][3];
            if (EPI == EPI_ELU) {
                v00 = v00 > 0.f ? v00 : expm1f(v00);
                v01 = v01 > 0.f ? v01 : expm1f(v01);
                v10 = v10 > 0.f ? v10 : expm1f(v10);
                v11 = v11 > 0.f ? v11 : expm1f(v11);
            } else if (EPI == EPI_RESID) {
                const float g0 = e2[col], g1 = e2[col + 1];
                const size_t r0 = (size_t)row * ldc + col;
                const size_t r1 = (size_t)(row + 8) * ldc + col;
                v00 = e1p[r0] + g0 * v00; v01 = e1p[r0 + 1] + g1 * v01;
                v10 = e1p[r1] + g0 * v10; v11 = e1p[r1 + 1] + g1 * v11;
            }
            const size_t o0 = (size_t)row * ldc + col;
            const size_t o1 = (size_t)(row + 8) * ldc + col;
            if (OUT == OUT_CONNECT) {
                const float sc0 = e1p[col], sc1 = e1p[col + 1];
                uchar2 c0, c1;
                c0.x = (v00 > 0.f && sr0 > 0.5f && sc0 > 0.5f) ? 1 : 0;
                c0.y = (v01 > 0.f && sr0 > 0.5f && sc1 > 0.5f) ? 1 : 0;
                c1.x = (v10 > 0.f && sr1 > 0.5f && sc0 > 0.5f) ? 1 : 0;
                c1.y = (v11 > 0.f && sr1 > 0.5f && sc1 > 0.5f) ? 1 : 0;
                *reinterpret_cast<uchar2*>(Cp8 + o0) = c0;
                *reinterpret_cast<uchar2*>(Cp8 + o1) = c1;
            } else if (OUT == OUT_F32) {
                *reinterpret_cast<float2*>(Cpf + o0) = make_float2(v00, v01);
                *reinterpret_cast<float2*>(Cpf + o1) = make_float2(v10, v11);
            }
            __nv_bfloat16 h00, l00, h01, l01, h10, l10, h11, l11;
            if (OUT == OUT_PLANES || DUAL) {
                split1(v00, h00, l00); split1(v01, h01, l01);
                split1(v10, h10, l10); split1(v11, h11, l11);
            }
            if (OUT == OUT_PLANES) {
                *reinterpret_cast<uint32_t*>(Cpb + o0) = pack2(h00, h01);
                *reinterpret_cast<uint32_t*>(Cpb + o1) = pack2(h10, h11);
                *reinterpret_cast<uint32_t*>(Cpb + cPlane + o0) = pack2(l00, l01);
                *reinterpret_cast<uint32_t*>(Cpb + cPlane + o1) = pack2(l10, l11);
            }
            if (DUAL) {
                const int cl = col - n0, rlc = row - m0;
                stg[cl * STR + rlc] = h00;
                stg[(cl + 1) * STR + rlc] = h01;
                stg[cl * STR + rlc + 8] = h10;
                stg[(cl + 1) * STR + rlc + 8] = h11;
                stg[STGPL + cl * STR + rlc] = l00;
                stg[STGPL + (cl + 1) * STR + rlc] = l01;
                stg[STGPL + cl * STR + rlc + 8] = l10;
                stg[STGPL + (cl + 1) * STR + rlc + 8] = l11;
            }
        }
    }
    if (DUAL) {
        __syncthreads();
        __nv_bfloat16* Ctp = Ct + (size_t)zb * sCtb + (size_t)zi * sCti;
        const int r = tid >> 1;
        const int hh = (tid & 1) * (BM / 2);
        #pragma unroll
        for (int p = 0; p < 2; p++) {
            const uint4* srow = reinterpret_cast<const uint4*>(stg + p * STGPL + r * STR + hh);
            uint4* drow = reinterpret_cast<uint4*>(Ctp + (size_t)p * ctPlane + (size_t)(n0 + r) * ldct + m0 + hh);
            #pragma unroll
            for (int i = 0; i < BM / 16; i++)
                drow[i] = srow[i];
        }
    }
}

// ---------------- fused flash cross-attention ----------------
#define QROWB 144
#define VROWB 272
#define QPLB (128*QROWB)
#define VPLB (64*VROWB)
#define FCA_SMEM (4*QPLB + 2*VPLB + 512)

__global__ void __launch_bounds__(256, 1)
k_flash_ca(const __nv_bfloat16* __restrict__ q2, const __nv_bfloat16* __restrict__ k2,
           const __nv_bfloat16* __restrict__ vT2, const float* __restrict__ sel,
           __nv_bfloat16* __restrict__ o2, long plane)
{
    extern __shared__ char smem[];
    const uint32_t sb = smem_u32(smem);
    const uint32_t Q0 = 0, K0 = 2 * QPLB, V0 = 4 * QPLB, SEL0 = 4 * QPLB + 2 * VPLB;
    const float* sel_s = reinterpret_cast<const float*>(smem + SEL0);

    const int tid = threadIdx.x, wid = tid >> 5, lane = tid & 31;
    const int b = blockIdx.y / HC, hc = blockIdx.y % HC;
    const int m0 = blockIdx.x * 128;

    const __nv_bfloat16* Qp = q2 + (size_t)b * ND + hc * DH;
    const __nv_bfloat16* Kp = k2 + (size_t)b * ND + hc * DH;
    const __nv_bfloat16* Vp = vT2 + (size_t)b * ND + (size_t)hc * DH * Nn;
    const float* selb = sel + b * Nn;

    {
        int row = tid >> 1, cb = (tid & 1) * 4;
        #pragma unroll
        for (int pl = 0; pl < 2; pl++)
            #pragma unroll
            for (int c = 0; c < 4; c++)
                CP16(sb + Q0 + pl * QPLB + row * QROWB + (cb + c) * 16,
                     Qp + (size_t)pl * plane + (size_t)(m0 + row) * Dd + (cb + c) * 8);
    }

    const int g = lane >> 3, rl = lane & 7;
    const int aRow = wid * 16 + (g & 1) * 8 + rl;
    const int aKs = (g >> 1) * 8;
    const int bRow = (g >> 1) * 8 + rl;
    const int bKs = (g & 1) * 8;
    const int q2c = (lane & 3) * 2;

    float O[8][4] = {};
    float mrow0 = -INFINITY, mrow1 = -INFINITY;
    float lrow0 = 0.f, lrow1 = 0.f;

    for (int kt = 0; kt < 8; kt++) {
        const int t0 = kt * 128;
        {
            int row = tid >> 1, cb = (tid & 1) * 4;
            #pragma unroll
            for (int pl = 0; pl < 2; pl++)
                #pragma unroll
                for (int c = 0; c < 4; c++)
                    CP16(sb + K0 + pl * QPLB + row * QROWB + (cb + c) * 16,
                         Kp + (size_t)pl * plane + (size_t)(t0 + row) * Dd + (cb + c) * 8);
            int vrow = tid >> 2, vcb = (tid & 3) * 4;
            #pragma unroll
            for (int pl = 0; pl < 2; pl++)
                #pragma unroll
                for (int c = 0; c < 4; c++)
                    CP16(sb + V0 + pl * VPLB + vrow * VROWB + (vcb + c) * 16,
                         Vp + (size_t)pl * plane + (size_t)vrow * Nn + t0 + (vcb + c) * 8);
            if (tid < 32)
                CP16(sb + SEL0 + tid * 16, selb + t0 + tid * 4);
        }
        CP_COMMIT();
        asm volatile("cp.async.wait_group 0;" ::: "memory");
        __syncthreads();

        float S[16][4];
        #pragma unroll
        for (int f = 0; f < 16; f++) { S[f][0] = S[f][1] = S[f][2] = S[f][3] = 0.f; }
        #pragma unroll
        for (int ks = 0; ks < 4; ks++) {
            uint32_t ah[4], al[4];
            ldsm4(ah, sb + Q0 + (uint32_t)(aRow * QROWB + (ks * 16 + aKs) * 2));
            ldsm4(al, sb + Q0 + QPLB + (uint32_t)(aRow * QROWB + (ks * 16 + aKs) * 2));
            #pragma unroll
            for (int nf2 = 0; nf2 < 8; nf2++) {
                uint32_t th[4], tl[4];
                ldsm4(th, sb + K0 + (uint32_t)((bRow + nf2 * 16) * QROWB + (ks * 16 + bKs) * 2));
                ldsm4(tl, sb + K0 + QPLB + (uint32_t)((bRow + nf2 * 16) * QROWB + (ks * 16 + bKs) * 2));
                uint32_t bh0[2] = {th[0], th[1]}, bh1[2] = {th[2], th[3]};
                uint32_t bl0[2] = {tl[0], tl[1]}, bl1[2] = {tl[2], tl[3]};
                mma16816(S[2 * nf2], ah, bh0);     mma16816(S[2 * nf2 + 1], ah, bh1);
                mma16816(S[2 * nf2], ah, bl0);     mma16816(S[2 * nf2 + 1], ah, bl1);
                mma16816(S[2 * nf2], al, bh0);     mma16816(S[2 * nf2 + 1], al, bh1);
            }
        }

        float mx0 = mrow0, mx1 = mrow1;
        #pragma unroll
        for (int f = 0; f < 16; f++) {
            int col = f * 8 + q2c;
            bool k0 = sel_s[col] > 0.5f, k1 = sel_s[col + 1] > 0.5f;
            S[f][0] = k0 ? S[f][0] * 0.125f : -1.0e9f;
            S[f][1] = k1 ? S[f][1] * 0.125f : -1.0e9f;
            S[f][2] = k0 ? S[f][2] * 0.125f : -1.0e9f;
            S[f][3] = k1 ? S[f][3] * 0.125f : -1.0e9f;
            mx0 = fmaxf(mx0, fmaxf(S[f][0], S[f][1]));
            mx1 = fmaxf(mx1, fmaxf(S[f][2], S[f][3]));
        }
        #pragma unroll
        for (int o = 1; o < 4; o <<= 1) {
            mx0 = fmaxf(mx0, __shfl_xor_sync(0xffffffffu, mx0, o));
            mx1 = fmaxf(mx1, __shfl_xor_sync(0xffffffffu, mx1, o));
        }
        const float sc0 = expf(mrow0 - mx0);
        const float sc1 = expf(mrow1 - mx1);
        mrow0 = mx0; mrow1 = mx1;
        lrow0 *= sc0; lrow1 *= sc1;
        #pragma unroll
        for (int f = 0; f < 8; f++) {
            O[f][0] *= sc0; O[f][1] *= sc0; O[f][2] *= sc1; O[f][3] *= sc1;
        }
        uint32_t P[8][4];
        float rs0 = 0.f, rs1 = 0.f;
        #pragma unroll
        for (int nf2 = 0; nf2 < 8; nf2++) {
            float p00 = expf(S[2 * nf2][0] - mx0),     p01 = expf(S[2 * nf2][1] - mx0);
            float p10 = expf(S[2 * nf2][2] - mx1),     p11 = expf(S[2 * nf2][3] - mx1);
            float p20 = expf(S[2 * nf2 + 1][0] - mx0), p21 = expf(S[2 * nf2 + 1][1] - mx0);
            float p30 = expf(S[2 * nf2 + 1][2] - mx1), p31 = expf(S[2 * nf2 + 1][3] - mx1);
            rs0 += p00 + p01 + p20 + p21;
            rs1 += p10 + p11 + p30 + p31;
            P[nf2][0] = packf2(p00, p01);
            P[nf2][1] = packf2(p10, p11);
            P[nf2][2] = packf2(p20, p21);
            P[nf2][3] = packf2(p30, p31);
        }
        #pragma unroll
        for (int o = 1; o < 4; o <<= 1) {
            rs0 += __shfl_xor_sync(0xffffffffu, rs0, o);
            rs1 += __shfl_xor_sync(0xffffffffu, rs1, o);
        }
        lrow0 += rs0; lrow1 += rs1;

        #pragma unroll
        for (int ks2 = 0; ks2 < 8; ks2++) {
            #pragma unroll
            for (int dn = 0; dn < 4; dn++) {
                uint32_t th[4], tl[4];
                ldsm4(th, sb + V0 + (uint32_t)((bRow + dn * 16) * VROWB + (ks2 * 16 + bKs) * 2));
                ldsm4(tl, sb + V0 + VPLB + (uint32_t)((bRow + dn * 16) * VROWB + (ks2 * 16 + bKs) * 2));
                uint32_t bh0[2] = {th[0], th[1]}, bh1[2] = {th[2], th[3]};
                uint32_t bl0[2] = {tl[0], tl[1]}, bl1[2] = {tl[2], tl[3]};
                mma16816(O[2 * dn],     P[ks2], bh0);
                mma16816(O[2 * dn + 1], P[ks2], bh1);
                mma16816(O[2 * dn],     P[ks2], bl0);
                mma16816(O[2 * dn + 1], P[ks2], bl1);
            }
        }
        __syncthreads();
    }

    const float li0 = 1.f / lrow0, li1 = 1.f / lrow1;
    const int row0 = m0 + wid * 16 + (lane >> 2);
    __nv_bfloat16* ob = o2 + (size_t)b * ND;
    #pragma unroll
    for (int f = 0; f < 8; f++) {
        int d = hc * DH + f * 8 + q2c;
        float v00 = O[f][0] * li0, v01 = O[f][1] * li0;
        float v10 = O[f][2] * li1, v11 = O[f][3] * li1;
        __nv_bfloat16 h00, l00, h01, l01, h10, l10, h11, l11;
        split1(v00, h00, l00); split1(v01, h01, l01);
        split1(v10, h10, l10); split1(v11, h11, l11);
        size_t o0 = (size_t)row0 * Dd + d;
        size_t o1 = (size_t)(row0 + 8) * Dd + d;
        *reinterpret_cast<uint32_t*>(ob + o0) = pack2(h00, h01);
        *reinterpret_cast<uint32_t*>(ob + o1) = pack2(h10, h11);
        *reinterpret_cast<uint32_t*>(ob + plane + o0) = pack2(l00, l01);
        *reinterpret_cast<uint32_t*>(ob + plane + o1) = pack2(l10, l11);
    }
}

// ---------------- auxiliary kernels ----------------
__global__ void k_posquery1(const float* __restrict__ x, const int* __restrict__ mask,
                            float* __restrict__ part, float* __restrict__ cntp)
{
    int seg = blockIdx.x, b = blockIdx.y, d = threadIdx.x;
    int n0 = seg * 64;
    float s = 0.f, cnt = 0.f;
    for (int n = n0; n < n0 + 64; n++) {
        if (mask[b * Nn + n] == 1) { s += x[((size_t)b * Nn + n) * Dd + d]; cnt += 1.f; }
    }
    part[((size_t)b * 16 + seg) * Dd + d] = s;
    if (d == 0) cntp[b * 16 + seg] = cnt;
}
__global__ void k_posquery2(const float* __restrict__ part, const float* __restrict__ cntp,
                            float* __restrict__ pq)
{
    int b = blockIdx.x, d = threadIdx.x;
    float s = 0.f, cnt = 0.f;
    #pragma unroll
    for (int seg = 0; seg < 16; seg++) {
        s += part[((size_t)b * 16 + seg) * Dd + d];
        cnt += cntp[b * 16 + seg];
    }
    pq[b * Dd + d] = s / fmaxf(cnt, 1.f);
}

__global__ void k_mv1(const float* __restrict__ Wq, const float* __restrict__ pq,
                      float* __restrict__ qs)
{
    __shared__ float spq[Dd];
    __shared__ float red[8][32];
    int b = blockIdx.y, t0 = blockIdx.x * 32;
    int tid = threadIdx.x;
    spq[tid] = pq[b * Dd + tid];
    __syncthreads();
    int tseg = tid >> 5, tl = tid & 31;
    float s = 0.f;
    #pragma unroll
    for (int i = 0; i < 32; i++)
        s += spq[tseg * 32 + i] * Wq[(tseg * 32 + i) * Dd + t0 + tl];
    red[tseg][tl] = s;
    __syncthreads();
    if (tseg == 0) {
        float a = 0.f;
        #pragma unroll
        for (int k = 0; k < 8; k++) a += red[k][tl];
        qs[b * Dd + t0 + tl] = a;
    }
}
__global__ void k_mv2(const float* __restrict__ Wx, const float* __restrict__ qs,
                      float* __restrict__ w)
{
    int b = blockIdx.y;
    int wid = threadIdx.x >> 5, lane = threadIdx.x & 31;
    int t = blockIdx.x * 8 + wid;
    float s = 0.f;
    #pragma unroll
    for (int k = 0; k < 8; k++)
        s += Wx[(size_t)t * Dd + lane + 32 * k] * qs[b * Dd + lane + 32 * k];
    #pragma unroll
    for (int o = 16; o; o >>= 1) s += __shfl_xor_sync(0xffffffffu, s, o);
    if (lane == 0) w[b * Dd + t] = s;
}

__global__ void k_possim(const float* __restrict__ x, const float* __restrict__ w,
                         float* __restrict__ possim_out, float* __restrict__ sel)
{
    int row = blockIdx.x * 8 + (threadIdx.x >> 5);
    int lane = threadIdx.x & 31;
    int b = row / Nn;
    const float4* xr = reinterpret_cast<const float4*>(x + (size_t)row * Dd);
    const float4* wr = reinterpret_cast<const float4*>(w + b * Dd);
    float s = 0.f;
    #pragma unroll
    for (int e = 0; e < 2; e++) {
        float4 xv = xr[lane + e * 32];
        float4 wv = wr[lane + e * 32];
        s += xv.x * wv.x + xv.y * wv.y + xv.z * wv.z + xv.w * wv.w;
    }
    #pragma unroll
    for (int o = 16; o; o >>= 1) s += __shfl_xor_sync(0xffffffffu, s, o);
    if (lane == 0) {
        float p = 1.f / (1.f + expf(-s * 0.0625f));
        possim_out[row] = p;
        sel[row] = (p > 0.97f) ? 1.f : 0.f;
    }
}

__global__ void k_dot2p(const __nv_bfloat16* __restrict__ rows, long plane,
                        const float* __restrict__ a1, const float* __restrict__ a2,
                        float* __restrict__ s1, float* __restrict__ s2, int nheads)
{
    int row = blockIdx.x * 8 + (threadIdx.x >> 5);
    int lane = threadIdx.x & 31;
    int head = (row / Nn) % nheads;
    const __nv_bfloat16* rp = rows + (size_t)row * Dd;
    const float* a1p = a1 + head * Dd;
    const float* a2p = a2 + head * Dd;
    float u = 0.f, v = 0.f;
    for (int e = lane; e < Dd; e += 32) {
        float rv = __bfloat162float(rp[e]) + __bfloat162float(rp[plane + e]);
        u += rv * a1p[e];
        v += rv * a2p[e];
    }
    #pragma unroll
    for (int o = 16; o; o >>= 1) {
        u += __shfl_xor_sync(0xffffffffu, u, o);
        v += __shfl_xor_sync(0xffffffffu, v, o);
    }
    if (lane == 0) { s1[row] = u; s2[row] = v; }
}

__global__ void k_softmax_gat(const float* __restrict__ s1, const float* __restrict__ s2,
                              const uint8_t* __restrict__ connect, __nv_bfloat16* __restrict__ attn,
                              int nheads)
{
    __shared__ float s2row[Nn];
    __shared__ float r8[8];
    int z = blockIdx.y;
    int b = z / nheads;
    int t = threadIdx.x;
    int wid = t >> 5, lane = t & 31;
    #pragma unroll
    for (int k = 0; k < 4; k++) s2row[t + k * 256] = s2[(size_t)z * Nn + t + k * 256];
    __syncthreads();
    #pragma unroll
    for (int r = 0; r < 4; r++) {
        int i = blockIdx.x * 4 + r;
        const uint8_t* con = connect + (size_t)b * NNt + (size_t)i * Nn;
        float s1v = s1[(size_t)z * Nn + i];
        float v[4];
        float mx = -INFINITY;
        #pragma unroll
        for (int k = 0; k < 4; k++) {
            int j = t + k * 256;
            float e = s1v + s2row[j];
            e = (e >= 0.f) ? e : 0.2f * e;
            v[k] = con[j] ? e : -9.0e15f;
            mx = fmaxf(mx, v[k]);
        }
        mx = bred<true>(mx, r8, wid, lane);
        float sum = 0.f;
        #pragma unroll
        for (int k = 0; k < 4; k++) { v[k] = expf(v[k] - mx); sum += v[k]; }
        sum = bred<false>(sum, r8, wid, lane);
        float inv = 1.f / sum;
        __nv_bfloat16* out = attn + (size_t)z * NNt + (size_t)i * Nn;
        #pragma unroll
        for (int k = 0; k < 4; k++) out[t + k * 256] = __float2bfloat16(v[k] * inv);
        __syncthreads();
    }
}

__global__ void k_ln(const float* __restrict__ in, const float* __restrict__ g,
                     const float* __restrict__ bb, __nv_bfloat16* __restrict__ out, long oplane)
{
    int row = blockIdx.x * 8 + (threadIdx.x >> 5);
    int lane = threadIdx.x & 31;
    size_t base = (size_t)row * Dd;
    float vbuf[8];
    float s = 0.f, sq = 0.f;
    #pragma unroll
    for (int k = 0; k < 8; k++) {
        float x = in[base + lane + k * 32];
        vbuf[k] = x; s += x; sq += x * x;
    }
    #pragma unroll
    for (int o = 16; o; o >>= 1) {
        s += __shfl_xor_sync(0xffffffffu, s, o);
        sq += __shfl_xor_sync(0xffffffffu, sq, o);
    }
    float mean = s * (1.f / Dd);
    float var = sq * (1.f / Dd) - mean * mean;
    float rstd = rsqrtf(var + 1e-5f);
    #pragma unroll
    for (int k = 0; k < 8; k++) {
        int d = lane + k * 32;
        float y = (vbuf[k] - mean) * rstd * g[d] + bb[d];
        __nv_bfloat16 h, l; split1(y, h, l);
        out[base + d] = h; out[oplane + base + d] = l;
    }
}

__global__ void k_qfull_ln(const __nv_bfloat16* __restrict__ gout, long gplane,
                           const float* __restrict__ pe,
                           const float* __restrict__ sel, const float* __restrict__ g,
                           const float* __restrict__ bb, __nv_bfloat16* __restrict__ out, long oplane)
{
    int row = blockIdx.x * 8 + (threadIdx.x >> 5);
    int lane = threadIdx.x & 31;
    int n = row % Nn;
    size_t base = (size_t)row * Dd;
    float selv = sel[row];
    float vbuf[8];
    float s = 0.f, sq = 0.f;
    #pragma unroll
    for (int k = 0; k < 8; k++) {
        int d = lane + k * 32;
        float gv = __bfloat162float(gout[base + d]) + __bfloat162float(gout[gplane + base + d]);
        float x = (selv > 0.5f) ? (gv + pe[(size_t)n * Dd + d]) : 0.f;
        vbuf[k] = x; s += x; sq += x * x;
    }
    #pragma unroll
    for (int o = 16; o; o >>= 1) {
        s += __shfl_xor_sync(0xffffffffu, s, o);
        sq += __shfl_xor_sync(0xffffffffu, sq, o);
    }
    float mean = s * (1.f / Dd);
    float var = sq * (1.f / Dd) - mean * mean;
    float rstd = rsqrtf(var + 1e-5f);
    #pragma unroll
    for (int k = 0; k < 8; k++) {
        int d = lane + k * 32;
        float y = (vbuf[k] - mean) * rstd * g[d] + bb[d];
        __nv_bfloat16 h, l; split1(y, h, l);
        out[base + d] = h; out[oplane + base + d] = l;
    }
}

// ---------------- launch ----------------
#define GETSYM(p, T, s) do { void* _t; cudaGetSymbolAddress(&_t, s); p = (T*)_t; } while (0)
#define SMEMSZ(BM, BN, NA, ST) (((ST) * (NA) * (BM) + (ST) * 2 * (BN)) * ROWB)

extern "C" void kernel_launch(void* const* d_in, const int* in_sizes, int n_in,
                              void* d_out, int out_size)
{
    const float* x      = (const float*)d_in[0];
    const int*   mask   = (const int*)  d_in[1];
    const float* pe     = (const float*)d_in[2];
    const float* simWx  = (const float*)d_in[3];
    const float* simWq  = (const float*)d_in[4];
    const float* adjW   = (const float*)d_in[5];
    const float* gatW   = (const float*)d_in[6];
    const float* gatA1  = (const float*)d_in[7];
    const float* gatA2  = (const float*)d_in[8];
    const float* gatWo  = (const float*)d_in[9];
    const float* gatAo1 = (const float*)d_in[10];
    const float* gatAo2 = (const float*)d_in[11];
    const float* ln3g   = (const float*)d_in[12];
    const float* ln3b   = (const float*)d_in[13];
    const float* ln4g   = (const float*)d_in[14];
    const float* ln4b   = (const float*)d_in[15];
    const float* caWq   = (const float*)d_in[16];
    const float* caWk   = (const float*)d_in[17];
    const float* caWv   = (const float*)d_in[18];
    const float* caWp   = (const float*)d_in[19];
    const float* gamma  = (const float*)d_in[20];
    (void)in_sizes; (void)n_in; (void)out_size;

    float* out = (float*)d_out;
    float* possim_out = out + (size_t)Bz * Nn * Dd;

    float *posq, *pqpart, *pqcnt, *qsv, *w, *sel, *s1, *s2, *so1, *so2;
    uint8_t* connect;
    __nv_bfloat16 *attn_bf, *attno_bf;
    __nv_bfloat16 *x2, *fa2, *Wh2, *WhT2, *cat2, *Who2, *WhoT2, *gout2, *qx2, *kv2;
    __nv_bfloat16 *q2, *k2, *vT2, *o2;
    __nv_bfloat16 *adjWT2, *gatWT2, *WoT2, *caWqT2, *caWkT2, *caWvT2, *caWpT2;
    GETSYM(posq, float, g_posq);   GETSYM(pqpart, float, g_pqpart); GETSYM(pqcnt, float, g_pqcnt);
    GETSYM(qsv, float, g_qs);      GETSYM(w, float, g_w);       GETSYM(sel, float, g_sel);
    GETSYM(connect, uint8_t, g_connect);
    GETSYM(s1, float, g_s1);       GETSYM(s2, float, g_s2);
    GETSYM(so1, float, g_so1);     GETSYM(so2, float, g_so2);
    GETSYM(attn_bf, __nv_bfloat16, g_attn_bf);
    GETSYM(attno_bf, __nv_bfloat16, g_attno_bf);
    GETSYM(x2, __nv_bfloat16, g_x2);     GETSYM(fa2, __nv_bfloat16, g_fa2);
    GETSYM(Wh2, __nv_bfloat16, g_Wh2);   GETSYM(WhT2, __nv_bfloat16, g_WhT2);
    GETSYM(cat2, __nv_bfloat16, g_cat2);
    GETSYM(Who2, __nv_bfloat16, g_Who2); GETSYM(WhoT2, __nv_bfloat16, g_WhoT2);
    GETSYM(gout2, __nv_bfloat16, g_gout2);
    GETSYM(qx2, __nv_bfloat16, g_qx2);   GETSYM(kv2, __nv_bfloat16, g_kv2);
    GETSYM(q2, __nv_bfloat16, g_q2);     GETSYM(k2, __nv_bfloat16, g_k2);
    GETSYM(vT2, __nv_bfloat16, g_vT2);   GETSYM(o2, __nv_bfloat16, g_o2);
    GETSYM(adjWT2, __nv_bfloat16, g_adjWT2); GETSYM(gatWT2, __nv_bfloat16, g_gatWT2);
    GETSYM(WoT2, __nv_bfloat16, g_WoT2);
    GETSYM(caWqT2, __nv_bfloat16, g_caWqT2); GETSYM(caWkT2, __nv_bfloat16, g_caWkT2);
    GETSYM(caWvT2, __nv_bfloat16, g_caWvT2); GETSYM(caWpT2, __nv_bfloat16, g_caWpT2);

    const long PL_BND  = (long)Bz * ND;
    const long PL_BHND = (long)Bz * Hh * ND;
    const long PL_CAT  = (long)Bz * Nn * HD;
    const long PL_DD   = (long)Dd * Dd;
    const long PL_GATW = (long)Hh * Dd * Dd;
    const long PL_WO   = (long)HD * Dd;

    const int SM_M2_22 = SMEMSZ(64, 128, 2, 2);    // 61440
    const int SM_M2_12 = SMEMSZ(64, 128, 1, 2);    // 51200
    const int SM_M4_22 = SMEMSZ(128, 128, 2, 2);   // 81920
    const int SM_M4_12 = SMEMSZ(128, 128, 1, 2);   // 61440
    cudaFuncSetAttribute(mma_gemm<2,128,2,4,EPI_NONE,   2,OUT_PLANES, false,2>, cudaFuncAttributeMaxDynamicSharedMemorySize, SM_M2_22);
    cudaFuncSetAttribute(mma_gemm<2,128,2,4,EPI_NONE,   2,OUT_PLANES, true ,2>, cudaFuncAttributeMaxDynamicSharedMemorySize, SM_M2_22);
    cudaFuncSetAttribute(mma_gemm<2,128,2,4,EPI_NONE,   2,OUT_NONE,   true ,2>, cudaFuncAttributeMaxDynamicSharedMemorySize, SM_M2_22);
    cudaFuncSetAttribute(mma_gemm<2,128,2,4,EPI_RESID,  2,OUT_F32,    false,2>, cudaFuncAttributeMaxDynamicSharedMemorySize, SM_M2_22);
    cudaFuncSetAttribute(mma_gemm<2,128,2,4,EPI_ELU,    1,OUT_PLANES, false,2>, cudaFuncAttributeMaxDynamicSharedMemorySize, SM_M2_12);
    cudaFuncSetAttribute(mma_gemm<4,128,2,4,EPI_NONE,   2,OUT_PLANES, true ,2>, cudaFuncAttributeMaxDynamicSharedMemorySize, SM_M4_22);
    cudaFuncSetAttribute(mma_gemm<4,128,2,4,EPI_CONNECT,2,OUT_CONNECT,false,2>, cudaFuncAttributeMaxDynamicSharedMemorySize, SM_M4_22);
    cudaFuncSetAttribute(mma_gemm<4,128,2,4,EPI_ELU,    1,OUT_PLANES, false,2>, cudaFuncAttributeMaxDynamicSharedMemorySize, SM_M4_12);
    cudaFuncSetAttribute(k_flash_ca, cudaFuncAttributeMaxDynamicSharedMemorySize, FCA_SMEM);

    const long zero = 0;
    cudaStream_t s0 = 0;
    cudaStream_t sA = hx.s1;
    cudaStream_t sB = hx.s2;

    // fork
    cudaEventRecord(hx.e0, s0);
    cudaStreamWaitEvent(sA, hx.e0, 0);
    cudaStreamWaitEvent(sB, hx.e0, 0);

    // stream B: weight transposes -> LN3 -> q projection
    k_transpose_all<<<1344, dim3(32, 8), 0, sB>>>(adjW, adjWT2, caWq, caWqT2, caWk, caWkT2,
                                                  caWv, caWvT2, caWp, caWpT2, gatW, gatWT2, gatWo, WoT2);
    cudaEventRecord(hx.eT, sB);
    k_ln<<<Bz * Nn / 8, 256, 0, sB>>>(x, ln3g, ln3b, qx2, PL_BND);

    // stream 0: split x
    k_split<<<Bz * ND / 1024, 256, 0, s0>>>(x, x2, PL_BND);
    cudaEventRecord(hx.eX, s0);

    // stream B: q = qx @ caWq   (BM=64, 256 CTAs)
    mma_gemm<2,128,2,4,EPI_NONE,2,OUT_PLANES,false,2><<<dim3(2, 128, 1), 256, SM_M2_22, sB>>>(
        qx2, PL_BND, caWqT2, PL_DD, q2, PL_BND,
        Dd, Dd, Dd, Dd, 1, zero, zero, zero, zero, zero, zero,
        nullptr, zero, nullptr, nullptr, zero, zero, zero, 0);
    cudaEventRecord(hx.eQ, sB);

    // stream A: selection path, then fa -> connect
    k_posquery1<<<dim3(16, Bz), 256, 0, sA>>>(x, mask, pqpart, pqcnt);
    k_posquery2<<<Bz, 256, 0, sA>>>(pqpart, pqcnt, posq);
    k_mv1<<<dim3(8, Bz), 256, 0, sA>>>(simWq, posq, qsv);
    k_mv2<<<dim3(32, Bz), 256, 0, sA>>>(simWx, qsv, w);
    k_possim<<<Bz * Nn / 8, 256, 0, sA>>>(x, w, possim_out, sel);
    cudaStreamWaitEvent(sA, hx.eX, 0);
    cudaStreamWaitEvent(sA, hx.eT, 0);
    mma_gemm<2,128,2,4,EPI_NONE,2,OUT_PLANES,false,2><<<dim3(2, 128, 1), 256, SM_M2_22, sA>>>(
        x2, PL_BND, adjWT2, PL_DD, fa2, PL_BND,
        Dd, Dd, Dd, Dd, 1, zero, zero, zero, zero, zero, zero,
        nullptr, zero, nullptr, nullptr, zero, zero, zero, 0);
    mma_gemm<4,128,2,4,EPI_CONNECT,2,OUT_CONNECT,false,2><<<dim3(8, 8, Bz), 256, SM_M4_22, sA>>>(
        fa2, PL_BND, fa2, PL_BND, connect, zero,
        Dd, Dd, Dd, Nn, 1, (long)ND, zero, (long)ND, zero, (long)NNt, zero,
        sel, (long)Nn, nullptr, nullptr, zero, zero, zero, 0);
    cudaEventRecord(hx.eConn, sA);

    // stream 0: main chain
    cudaStreamWaitEvent(s0, hx.eT, 0);

    mma_gemm<4,128,2,4,EPI_NONE,2,OUT_PLANES,true,2><<<dim3(2, 8, Bz * Hh), 256, SM_M4_22, s0>>>(
        x2, PL_BND, gatWT2, PL_GATW, Wh2, PL_BHND,
        Dd, Dd, Dd, Dd, Hh, (long)ND, zero, zero, (long)Dd * Dd,
        (long)Hh * ND, (long)ND,
        nullptr, zero, nullptr, WhT2, PL_BHND, (long)Hh * ND, (long)ND, Nn);

    k_dot2p<<<Bz * Hh * Nn / 8, 256, 0, s0>>>(Wh2, PL_BHND, gatA1, gatA2, s1, s2, Hh);

    cudaStreamWaitEvent(s0, hx.eConn, 0);
    k_softmax_gat<<<dim3(Nn / 4, Bz * Hh), 256, 0, s0>>>(s1, s2, connect, attn_bf, Hh);

    mma_gemm<4,128,2,4,EPI_ELU,1,OUT_PLANES,false,2><<<dim3(2, 8, Bz * Hh), 256, SM_M4_12, s0>>>(
        attn_bf, zero, WhT2, PL_BHND, cat2, PL_CAT,
        Nn, Nn, Nn, HD, Hh, (long)Hh * NNt, (long)NNt, (long)Hh * ND, (long)ND,
        (long)Nn * HD, (long)Dd,
        nullptr, zero, nullptr, nullptr, zero, zero, zero, 0);

    // Who: BM=64 -> 256 CTAs
    mma_gemm<2,128,2,4,EPI_NONE,2,OUT_PLANES,true,2><<<dim3(2, 16, Bz), 256, SM_M2_22, s0>>>(
        cat2, PL_CAT, WoT2, PL_WO, Who2, PL_BND,
        HD, HD, HD, Dd, 1, (long)Nn * HD, zero, zero, zero, (long)ND, zero,
        nullptr, zero, nullptr, WhoT2, PL_BND, (long)ND, zero, Nn);

    k_dot2p<<<Bz * Nn / 8, 256, 0, s0>>>(Who2, PL_BND, gatAo1, gatAo2, so1, so2, 1);
    k_softmax_gat<<<dim3(Nn / 4, Bz), 256, 0, s0>>>(so1, so2, connect, attno_bf, 1);

    // gout: BM=64 -> 256 CTAs
    mma_gemm<2,128,2,4,EPI_ELU,1,OUT_PLANES,false,2><<<dim3(2, 16, Bz), 256, SM_M2_12, s0>>>(
        attno_bf, zero, WhoT2, PL_BND, gout2, PL_BND,
        Nn, Nn, Nn, Dd, 1, (long)NNt, zero, (long)ND, zero, (long)ND, zero,
        nullptr, zero, nullptr, nullptr, zero, zero, zero, 0);

    k_qfull_ln<<<Bz * Nn / 8, 256, 0, s0>>>(gout2, PL_BND, pe, sel, ln4g, ln4b, kv2, PL_BND);
    cudaEventRecord(hx.eKV, s0);

    // stream B: k projection (parallel with vT on s0)
    cudaStreamWaitEvent(sB, hx.eKV, 0);
    mma_gemm<2,128,2,4,EPI_NONE,2,OUT_PLANES,false,2><<<dim3(2, 128, 1), 256, SM_M2_22, sB>>>(
        kv2, PL_BND, caWkT2, PL_DD, k2, PL_BND,
        Dd, Dd, Dd, Dd, 1, zero, zero, zero, zero, zero, zero,
        nullptr, zero, nullptr, nullptr, zero, zero, zero, 0);
    cudaEventRecord(hx.eK, sB);

    // stream 0: v projection (transposed planes only), BM=64
    mma_gemm<2,128,2,4,EPI_NONE,2,OUT_NONE,true,2><<<dim3(2, 16, Bz), 256, SM_M2_22, s0>>>(
        kv2, PL_BND, caWvT2, PL_DD, nullptr, zero,
        Dd, Dd, Dd, Dd, 1, (long)ND, zero, zero, zero, (long)ND, zero,
        nullptr, zero, nullptr, vT2, PL_BND, (long)ND, zero, Nn);

    // fused flash CA
    cudaStreamWaitEvent(s0, hx.eQ, 0);
    cudaStreamWaitEvent(s0, hx.eK, 0);
    k_flash_ca<<<dim3(Nn / 128, Bz * HC), 256, FCA_SMEM, s0>>>(
        q2, k2, vT2, sel, o2, PL_BND);

    // out = x + gamma * (o @ caWp), BM=64
    mma_gemm<2,128,2,4,EPI_RESID,2,OUT_F32,false,2><<<dim3(2, 128, 1), 256, SM_M2_22, s0>>>(
        o2, PL_BND, caWpT2, PL_DD, out, zero,
        Dd, Dd, Dd, Dd, 1, zero, zero, zero, zero, zero, zero,
        x, zero, gamma, nullptr, zero, zero, zero, 0);
}

// round 14
// speedup vs baseline: 1.0962x; 1.0962x over previous
#include <cuda_runtime.h>
#include <cuda_bf16.h>
#include <math.h>
#include <stdint.h>

// Problem constants
#define Bz 8
#define Nn 1024
#define Dd 256
#define Hh 8
#define HC 4
#define DH 64
#define HD 2048                 // Hh*Dd
#define ND (Nn*Dd)              // 262144
#define NNt ((size_t)Nn*Nn)     // 1048576

// ---------------- scratch (device globals) ----------------
__device__ float g_posq[Bz*Dd];
__device__ float g_pqpart[Bz*16*Dd];
__device__ float g_pqcnt[Bz*16];
__device__ float g_qs[Bz*Dd];
__device__ float g_w[Bz*Dd];
__device__ float g_sel[Bz*Nn];
__device__ uint8_t g_connect[(size_t)Bz*Nn*Nn];
__device__ float g_s1[Bz*Hh*Nn];
__device__ float g_s2[Bz*Hh*Nn];
__device__ float g_so1[Bz*Nn];
__device__ float g_so2[Bz*Nn];
__device__ __nv_bfloat16 g_attn_bf[(size_t)Bz*Hh*Nn*Nn];   // GAT probs
__device__ __nv_bfloat16 g_attno_bf[(size_t)Bz*Nn*Nn];

__device__ __nv_bfloat16 g_x2[2*(size_t)Bz*ND];
__device__ __nv_bfloat16 g_fa2[2*(size_t)Bz*ND];
__device__ __nv_bfloat16 g_Wh2[2*(size_t)Bz*Hh*ND];
__device__ __nv_bfloat16 g_WhT2[2*(size_t)Bz*Hh*ND];
__device__ __nv_bfloat16 g_cat2[2*(size_t)Bz*Nn*HD];
__device__ __nv_bfloat16 g_Who2[2*(size_t)Bz*ND];
__device__ __nv_bfloat16 g_WhoT2[2*(size_t)Bz*ND];
__device__ __nv_bfloat16 g_gout2[2*(size_t)Bz*ND];
__device__ __nv_bfloat16 g_qx2[2*(size_t)Bz*ND];
__device__ __nv_bfloat16 g_kv2[2*(size_t)Bz*ND];
__device__ __nv_bfloat16 g_q2[2*(size_t)Bz*ND];
__device__ __nv_bfloat16 g_k2[2*(size_t)Bz*ND];
__device__ __nv_bfloat16 g_vT2[2*(size_t)Bz*ND];
__device__ __nv_bfloat16 g_o2[2*(size_t)Bz*ND];
// transposed weights (planes)
__device__ __nv_bfloat16 g_adjWT2[2*Dd*Dd];
__device__ __nv_bfloat16 g_gatWT2[2*Hh*Dd*Dd];
__device__ __nv_bfloat16 g_WoT2[2*HD*Dd];
__device__ __nv_bfloat16 g_caWqT2[2*Dd*Dd];
__device__ __nv_bfloat16 g_caWkT2[2*Dd*Dd];
__device__ __nv_bfloat16 g_caWvT2[2*Dd*Dd];
__device__ __nv_bfloat16 g_caWpT2[2*Dd*Dd];

// ---------------- streams/events ----------------
struct HXStreams {
    cudaStream_t s1, s2;
    cudaEvent_t e0, eT, eX, eConn, eQ, eKV, eK;
    HXStreams() {
        cudaStreamCreateWithFlags(&s1, cudaStreamNonBlocking);
        cudaStreamCreateWithFlags(&s2, cudaStreamNonBlocking);
        cudaEventCreateWithFlags(&e0, cudaEventDisableTiming);
        cudaEventCreateWithFlags(&eT, cudaEventDisableTiming);
        cudaEventCreateWithFlags(&eX, cudaEventDisableTiming);
        cudaEventCreateWithFlags(&eConn, cudaEventDisableTiming);
        cudaEventCreateWithFlags(&eQ, cudaEventDisableTiming);
        cudaEventCreateWithFlags(&eKV, cudaEventDisableTiming);
        cudaEventCreateWithFlags(&eK, cudaEventDisableTiming);
    }
};
static HXStreams hx;

// ---------------- low-level helpers ----------------
__device__ __forceinline__ uint32_t smem_u32(const void* p) {
    uint32_t a;
    asm("{ .reg .u64 t; cvta.to.shared.u64 t, %1; cvt.u32.u64 %0, t; }" : "=r"(a) : "l"(p));
    return a;
}
__device__ __forceinline__ void ldsm4(uint32_t* r, uint32_t addr) {
    asm volatile("ldmatrix.sync.aligned.m8n8.x4.shared.b16 {%0,%1,%2,%3}, [%4];"
        : "=r"(r[0]), "=r"(r[1]), "=r"(r[2]), "=r"(r[3]) : "r"(addr));
}
__device__ __forceinline__ void mma16816(float* c, const uint32_t* a, const uint32_t* b) {
    asm volatile("mma.sync.aligned.m16n8k16.row.col.f32.bf16.bf16.f32 "
        "{%0,%1,%2,%3}, {%4,%5,%6,%7}, {%8,%9}, {%0,%1,%2,%3};"
        : "+f"(c[0]), "+f"(c[1]), "+f"(c[2]), "+f"(c[3])
        : "r"(a[0]), "r"(a[1]), "r"(a[2]), "r"(a[3]), "r"(b[0]), "r"(b[1]));
}
__device__ __forceinline__ void split1(float v, __nv_bfloat16& h, __nv_bfloat16& l) {
    h = __float2bfloat16(v);
    l = __float2bfloat16(v - __bfloat162float(h));
}
__device__ __forceinline__ uint32_t pack2(__nv_bfloat16 a, __nv_bfloat16 b) {
    return (uint32_t)__bfloat16_as_ushort(a) | ((uint32_t)__bfloat16_as_ushort(b) << 16);
}
__device__ __forceinline__ uint32_t packf2(float a, float b) {
    uint32_t r;
    asm("cvt.rn.bf16x2.f32 %0, %1, %2;" : "=r"(r) : "f"(b), "f"(a));
    return r;
}
#define CP16(dst, src) \
    asm volatile("cp.async.cg.shared.global [%0], [%1], 16;" :: "r"(dst), "l"(src))
#define CP_COMMIT() asm volatile("cp.async.commit_group;" ::: "memory")

template <bool MAX>
__device__ __forceinline__ float bred(float v, float* r8, int wid, int lane) {
    #pragma unroll
    for (int o = 16; o; o >>= 1) {
        float u = __shfl_xor_sync(0xffffffffu, v, o);
        v = MAX ? fmaxf(v, u) : (v + u);
    }
    if (lane == 0) r8[wid] = v;
    __syncthreads();
    if (wid == 0) {
        float u = r8[lane & 7];
        #pragma unroll
        for (int o = 4; o; o >>= 1) {
            float t = __shfl_xor_sync(0xffffffffu, u, o);
            u = MAX ? fmaxf(u, t) : (u + t);
        }
        if (lane == 0) r8[0] = u;
    }
    __syncthreads();
    return r8[0];
}

// ---------------- split x into planes ----------------
__global__ void k_split(const float* __restrict__ in, __nv_bfloat16* __restrict__ outp, long plane)
{
    int i = blockIdx.x * 256 + threadIdx.x;
    float4 v = reinterpret_cast<const float4*>(in)[i];
    __nv_bfloat16 h0, l0, h1, l1, h2, l2, h3, l3;
    split1(v.x, h0, l0); split1(v.y, h1, l1); split1(v.z, h2, l2); split1(v.w, h3, l3);
    reinterpret_cast<uint2*>(outp)[i] = make_uint2(pack2(h0, h1), pack2(h2, h3));
    reinterpret_cast<uint2*>(outp + plane)[i] = make_uint2(pack2(l0, l1), pack2(l2, l3));
}

// ---------------- merged transpose kernel ----------------
__global__ void k_transpose_all(const float* adjW, __nv_bfloat16* adjWT,
                                const float* caWq, __nv_bfloat16* caWqT,
                                const float* caWk, __nv_bfloat16* caWkT,
                                const float* caWv, __nv_bfloat16* caWvT,
                                const float* caWp, __nv_bfloat16* caWpT,
                                const float* gatW, __nv_bfloat16* gatWT,
                                const float* gatWo, __nv_bfloat16* WoT)
{
    __shared__ float t[32][33];
    int id = blockIdx.x;
    int tx = threadIdx.x, ty = threadIdx.y;
    const float* src; __nv_bfloat16* dh; long plane; int R, C, bx, by;
    if (id < 320) {
        const float* srcs[5] = {adjW, caWq, caWk, caWv, caWp};
        __nv_bfloat16* dsts[5] = {adjWT, caWqT, caWkT, caWvT, caWpT};
        int m = id >> 6, l = id & 63;
        src = srcs[m]; dh = dsts[m]; plane = Dd * Dd;
        R = Dd; C = Dd; bx = (l & 7) * 32; by = (l >> 3) * 32;
    } else if (id < 832) {
        int l = id - 320; int z = l >> 6; l &= 63;
        src = gatW + (size_t)z * Dd * Dd; dh = gatWT + (size_t)z * Dd * Dd;
        plane = (long)Hh * Dd * Dd;
        R = Dd; C = Dd; bx = (l & 7) * 32; by = (l >> 3) * 32;
    } else {
        int l = id - 832;
        src = gatWo; dh = WoT; plane = (long)HD * Dd;
        R = HD; C = Dd; bx = (l & 7) * 32; by = (l >> 3) * 32;
    }
    #pragma unroll
    for (int i = 0; i < 32; i += 8)
        t[ty + i][tx] = src[(size_t)(by + ty + i) * C + bx + tx];
    __syncthreads();
    #pragma unroll
    for (int i = 0; i < 32; i += 8) {
        float v = t[tx][ty + i];
        __nv_bfloat16 h, l2;
        split1(v, h, l2);
        size_t o = (size_t)(bx + ty + i) * R + by + tx;
        dh[o] = h; dh[plane + o] = l2;
    }
}

// ---------------- plane-pair bf16 mma.sync NT GEMM ----------------
// BM = WM * MF * 16. NA = A planes (1|2), NB = B planes (1|2).
enum { EPI_NONE = 0, EPI_ELU = 1, EPI_CONNECT = 2, EPI_RESID = 3 };
enum { OUT_F32 = 0, OUT_PLANES = 1, OUT_CONNECT = 2, OUT_NONE = 3 };
#define ROWB 80

template <int MF, int BN, int WM, int WN, int EPI, int NA, int NB, int OUT, bool DUAL>
__global__ void __launch_bounds__(256, 2)
mma_gemm(const __nv_bfloat16* __restrict__ A, long aPlane,
         const __nv_bfloat16* __restrict__ Bm, long bPlane,
         void* __restrict__ Cv, long cPlane,
         int K, int lda, int ldb, int ldc, int zInner,
         long sAb, long sAi, long sBb, long sBi, long sCb, long sCi,
         const float* __restrict__ e1, long sE1b, const float* __restrict__ e2,
         __nv_bfloat16* __restrict__ Ct, long ctPlane, long sCtb, long sCti, int ldct)
{
    constexpr int BM = WM * MF * 16;
    constexpr int ABYTES = BM * ROWB;
    constexpr int BBYTES = BN * ROWB;
    constexpr int STR = BM + 8;
    constexpr int STGPL = BN * STR;

    extern __shared__ char smem[];
    const uint32_t sb = smem_u32(smem);

    const int tid = threadIdx.x;
    const int wid = tid >> 5;
    const int lane = tid & 31;

    const int z = blockIdx.z;
    const int zb = z / zInner, zi = z % zInner;
    const __nv_bfloat16* Ap = A + (size_t)zb * sAb + (size_t)zi * sAi;
    const __nv_bfloat16* Bp = Bm + (size_t)zb * sBb + (size_t)zi * sBi;
    float* Cpf = (float*)Cv + (size_t)zb * sCb + (size_t)zi * sCi;
    __nv_bfloat16* Cpb = (__nv_bfloat16*)Cv + (size_t)zb * sCb + (size_t)zi * sCi;
    uint8_t* Cp8 = (uint8_t*)Cv + (size_t)zb * sCb + (size_t)zi * sCi;
    const float* e1p = e1 ? (e1 + (size_t)zb * sE1b) : nullptr;

    const int m0 = blockIdx.y * BM;
    const int n0 = blockIdx.x * BN;

    const int crow = tid >> 2;
    const int cch = tid & 3;

    const int wid_m = wid % WM;
    const int wid_n = wid / WM;
    const int g = lane >> 3, rl = lane & 7;
    const int aRowBase = wid_m * (MF * 16) + (g & 1) * 8 + rl;
    const int aKsel = (g >> 1) * 8;
    const int bRowBase = wid_n * 32 + (g >> 1) * 8 + rl;
    const int bKsel = (g & 1) * 8;

    float acc[MF][4][4] = {};
    const int nkt = K >> 5;
    const uint32_t bbase = 2 * NA * ABYTES;

    auto copyTile = [&](int kk, int stage) {
        #pragma unroll
        for (int pl = 0; pl < NA; pl++) {
            const __nv_bfloat16* src = Ap + (size_t)pl * aPlane;
            uint32_t dst0 = sb + (stage * NA + pl) * ABYTES;
            #pragma unroll
            for (int i = 0; i < BM / 64; i++) {
                int row = crow + 64 * i;
                CP16(dst0 + row * ROWB + cch * 16,
                     src + (size_t)(m0 + row) * lda + kk + cch * 8);
            }
        }
        #pragma unroll
        for (int pl = 0; pl < NB; pl++) {
            const __nv_bfloat16* src = Bp + (size_t)pl * bPlane;
            uint32_t dst0 = sb + bbase + (stage * NB + pl) * BBYTES;
            #pragma unroll
            for (int i = 0; i < BN / 64; i++) {
                int row = crow + 64 * i;
                CP16(dst0 + row * ROWB + cch * 16,
                     src + (size_t)(n0 + row) * ldb + kk + cch * 8);
            }
        }
    };

    copyTile(0, 0); CP_COMMIT();

    for (int kt = 0; kt < nkt; kt++) {
        const int stage = kt & 1;
        const bool more = (kt + 1 < nkt);
        if (more) { copyTile((kt + 1) << 5, (kt + 1) & 1); CP_COMMIT(); }
        if (more) asm volatile("cp.async.wait_group 1;" ::: "memory");
        else      asm volatile("cp.async.wait_group 0;" ::: "memory");
        __syncthreads();

        const uint32_t sAhi = sb + stage * NA * ABYTES;
        const uint32_t sAlo = sAhi + ABYTES;
        const uint32_t sBhi = sb + bbase + stage * NB * BBYTES;
        const uint32_t sBlo = sBhi + BBYTES;

        #pragma unroll
        for (int j = 0; j < 2; j++) {
            const int kb = j * 16;
            uint32_t a[MF][4], bh[4][2], bl[4][2];
            #pragma unroll
            for (int im = 0; im < MF; im++)
                ldsm4(a[im], sAhi + (uint32_t)((aRowBase + im * 16) * ROWB + (kb + aKsel) * 2));
            #pragma unroll
            for (int i2 = 0; i2 < 2; i2++) {
                uint32_t t[4];
                ldsm4(t, sBhi + (uint32_t)((bRowBase + i2 * 16) * ROWB + (kb + bKsel) * 2));
                bh[2 * i2][0] = t[0]; bh[2 * i2][1] = t[1];
                bh[2 * i2 + 1][0] = t[2]; bh[2 * i2 + 1][1] = t[3];
            }
            #pragma unroll
            for (int im = 0; im < MF; im++)
                #pragma unroll
                for (int in = 0; in < 4; in++)
                    mma16816(acc[im][in], a[im], bh[in]);           // Ah*Bh
            if (NB == 2) {
                #pragma unroll
                for (int i2 = 0; i2 < 2; i2++) {
                    uint32_t t[4];
                    ldsm4(t, sBlo + (uint32_t)((bRowBase + i2 * 16) * ROWB + (kb + bKsel) * 2));
                    bl[2 * i2][0] = t[0]; bl[2 * i2][1] = t[1];
                    bl[2 * i2 + 1][0] = t[2]; bl[2 * i2 + 1][1] = t[3];
                }
                #pragma unroll
                for (int im = 0; im < MF; im++)
                    #pragma unroll
                    for (int in = 0; in < 4; in++)
                        mma16816(acc[im][in], a[im], bl[in]);       // Ah*Bl
            }
            if (NA == 2) {
                #pragma unroll
                for (int im = 0; im < MF; im++)
                    ldsm4(a[im], sAlo + (uint32_t)((aRowBase + im * 16) * ROWB + (kb + aKsel) * 2));
                #pragma unroll
                for (int im = 0; im < MF; im++)
                    #pragma unroll
                    for (int in = 0; in < 4; in++)
                        mma16816(acc[im][in], a[im], bh[in]);       // Al*Bh
            }
        }
        __syncthreads();
    }

    // epilogue
    __nv_bfloat16* stg = reinterpret_cast<__nv_bfloat16*>(smem);
    const int mw = m0 + wid_m * (MF * 16);
    const int nw = n0 + wid_n * 32;
    #pragma unroll
    for (int im = 0; im < MF; im++) {
        const int row = mw + im * 16 + (lane >> 2);
        const float sr0 = (EPI == EPI_CONNECT) ? e1p[row] : 0.f;
        const float sr1 = (EPI == EPI_CONNECT) ? e1p[row + 8] : 0.f;
        #pragma unroll
        for (int in = 0; in < 4; in++) {
            const int col = nw + in * 8 + (lane & 3) * 2;
            float v00 = acc[im][in][0], v01 = acc[im][in][1];
            float v10 = acc[im][in][2], v11 = acc[im][in][3];
            if (EPI == EPI_ELU) {
                v00 = v00 > 0.f ? v00 : expm1f(v00);
                v01 = v01 > 0.f ? v01 : expm1f(v01);
                v10 = v10 > 0.f ? v10 : expm1f(v10);
                v11 = v11 > 0.f ? v11 : expm1f(v11);
            } else if (EPI == EPI_RESID) {
                const float g0 = e2[col], g1 = e2[col + 1];
                const size_t r0 = (size_t)row * ldc + col;
                const size_t r1 = (size_t)(row + 8) * ldc + col;
                v00 = e1p[r0] + g0 * v00; v01 = e1p[r0 + 1] + g1 * v01;
                v10 = e1p[r1] + g0 * v10; v11 = e1p[r1 + 1] + g1 * v11;
            }
            const size_t o0 = (size_t)row * ldc + col;
            const size_t o1 = (size_t)(row + 8) * ldc + col;
            if (OUT == OUT_CONNECT) {
                const float sc0 = e1p[col], sc1 = e1p[col + 1];
                uchar2 c0, c1;
                c0.x = (v00 > 0.f && sr0 > 0.5f && sc0 > 0.5f) ? 1 : 0;
                c0.y = (v01 > 0.f && sr0 > 0.5f && sc1 > 0.5f) ? 1 : 0;
                c1.x = (v10 > 0.f && sr1 > 0.5f && sc0 > 0.5f) ? 1 : 0;
                c1.y = (v11 > 0.f && sr1 > 0.5f && sc1 > 0.5f) ? 1 : 0;
                *reinterpret_cast<uchar2*>(Cp8 + o0) = c0;
                *reinterpret_cast<uchar2*>(Cp8 + o1) = c1;
            } else if (OUT == OUT_F32) {
                *reinterpret_cast<float2*>(Cpf + o0) = make_float2(v00, v01);
                *reinterpret_cast<float2*>(Cpf + o1) = make_float2(v10, v11);
            }
            __nv_bfloat16 h00, l00, h01, l01, h10, l10, h11, l11;
            if (OUT == OUT_PLANES || DUAL) {
                split1(v00, h00, l00); split1(v01, h01, l01);
                split1(v10, h10, l10); split1(v11, h11, l11);
            }
            if (OUT == OUT_PLANES) {
                *reinterpret_cast<uint32_t*>(Cpb + o0) = pack2(h00, h01);
                *reinterpret_cast<uint32_t*>(Cpb + o1) = pack2(h10, h11);
                *reinterpret_cast<uint32_t*>(Cpb + cPlane + o0) = pack2(l00, l01);
                *reinterpret_cast<uint32_t*>(Cpb + cPlane + o1) = pack2(l10, l11);
            }
            if (DUAL) {
                const int cl = col - n0, rlc = row - m0;
                stg[cl * STR + rlc] = h00;
                stg[(cl + 1) * STR + rlc] = h01;
                stg[cl * STR + rlc + 8] = h10;
                stg[(cl + 1) * STR + rlc + 8] = h11;
                stg[STGPL + cl * STR + rlc] = l00;
                stg[STGPL + (cl + 1) * STR + rlc] = l01;
                stg[STGPL + cl * STR + rlc + 8] = l10;
                stg[STGPL + (cl + 1) * STR + rlc + 8] = l11;
            }
        }
    }
    if (DUAL) {
        __syncthreads();
        __nv_bfloat16* Ctp = Ct + (size_t)zb * sCtb + (size_t)zi * sCti;
        const int r = tid >> 1;
        const int hh = (tid & 1) * (BM / 2);
        #pragma unroll
        for (int p = 0; p < 2; p++) {
            const uint4* srow = reinterpret_cast<const uint4*>(stg + p * STGPL + r * STR + hh);
            uint4* drow = reinterpret_cast<uint4*>(Ctp + (size_t)p * ctPlane + (size_t)(n0 + r) * ldct + m0 + hh);
            #pragma unroll
            for (int i = 0; i < BM / 16; i++)
                drow[i] = srow[i];
        }
    }
}

// ---------------- fused flash cross-attention (V plane-pair, R12 numerics) ----------------
#define QROWB 144
#define VROWB 272
#define QPLB (128*QROWB)
#define VPLB (64*VROWB)
#define FCA_SMEM (4*QPLB + 2*VPLB + 512)

__global__ void __launch_bounds__(256, 1)
k_flash_ca(const __nv_bfloat16* __restrict__ q2, const __nv_bfloat16* __restrict__ k2,
           const __nv_bfloat16* __restrict__ vT2, const float* __restrict__ sel,
           __nv_bfloat16* __restrict__ o2, long plane)
{
    extern __shared__ char smem[];
    const uint32_t sb = smem_u32(smem);
    const uint32_t Q0 = 0, K0 = 2 * QPLB, V0 = 4 * QPLB, SEL0 = 4 * QPLB + 2 * VPLB;
    const float* sel_s = reinterpret_cast<const float*>(smem + SEL0);

    const int tid = threadIdx.x, wid = tid >> 5, lane = tid & 31;
    const int b = blockIdx.y / HC, hc = blockIdx.y % HC;
    const int m0 = blockIdx.x * 128;

    const __nv_bfloat16* Qp = q2 + (size_t)b * ND + hc * DH;
    const __nv_bfloat16* Kp = k2 + (size_t)b * ND + hc * DH;
    const __nv_bfloat16* Vp = vT2 + (size_t)b * ND + (size_t)hc * DH * Nn;
    const float* selb = sel + b * Nn;

    {
        int row = tid >> 1, cb = (tid & 1) * 4;
        #pragma unroll
        for (int pl = 0; pl < 2; pl++)
            #pragma unroll
            for (int c = 0; c < 4; c++)
                CP16(sb + Q0 + pl * QPLB + row * QROWB + (cb + c) * 16,
                     Qp + (size_t)pl * plane + (size_t)(m0 + row) * Dd + (cb + c) * 8);
    }

    const int g = lane >> 3, rl = lane & 7;
    const int aRow = wid * 16 + (g & 1) * 8 + rl;
    const int aKs = (g >> 1) * 8;
    const int bRow = (g >> 1) * 8 + rl;
    const int bKs = (g & 1) * 8;
    const int q2c = (lane & 3) * 2;

    float O[8][4] = {};
    float mrow0 = -INFINITY, mrow1 = -INFINITY;
    float lrow0 = 0.f, lrow1 = 0.f;

    for (int kt = 0; kt < 8; kt++) {
        const int t0 = kt * 128;
        {
            int row = tid >> 1, cb = (tid & 1) * 4;
            #pragma unroll
            for (int pl = 0; pl < 2; pl++)
                #pragma unroll
                for (int c = 0; c < 4; c++)
                    CP16(sb + K0 + pl * QPLB + row * QROWB + (cb + c) * 16,
                         Kp + (size_t)pl * plane + (size_t)(t0 + row) * Dd + (cb + c) * 8);
            int vrow = tid >> 2, vcb = (tid & 3) * 4;
            #pragma unroll
            for (int pl = 0; pl < 2; pl++)
                #pragma unroll
                for (int c = 0; c < 4; c++)
                    CP16(sb + V0 + pl * VPLB + vrow * VROWB + (vcb + c) * 16,
                         Vp + (size_t)pl * plane + (size_t)vrow * Nn + t0 + (vcb + c) * 8);
            if (tid < 32)
                CP16(sb + SEL0 + tid * 16, selb + t0 + tid * 4);
        }
        CP_COMMIT();
        asm volatile("cp.async.wait_group 0;" ::: "memory");
        __syncthreads();

        float S[16][4];
        #pragma unroll
        for (int f = 0; f < 16; f++) { S[f][0] = S[f][1] = S[f][2] = S[f][3] = 0.f; }
        #pragma unroll
        for (int ks = 0; ks < 4; ks++) {
            uint32_t ah[4], al[4];
            ldsm4(ah, sb + Q0 + (uint32_t)(aRow * QROWB + (ks * 16 + aKs) * 2));
            ldsm4(al, sb + Q0 + QPLB + (uint32_t)(aRow * QROWB + (ks * 16 + aKs) * 2));
            #pragma unroll
            for (int nf2 = 0; nf2 < 8; nf2++) {
                uint32_t th[4], tl[4];
                ldsm4(th, sb + K0 + (uint32_t)((bRow + nf2 * 16) * QROWB + (ks * 16 + bKs) * 2));
                ldsm4(tl, sb + K0 + QPLB + (uint32_t)((bRow + nf2 * 16) * QROWB + (ks * 16 + bKs) * 2));
                uint32_t bh0[2] = {th[0], th[1]}, bh1[2] = {th[2], th[3]};
                uint32_t bl0[2] = {tl[0], tl[1]}, bl1[2] = {tl[2], tl[3]};
                mma16816(S[2 * nf2], ah, bh0);     mma16816(S[2 * nf2 + 1], ah, bh1);
                mma16816(S[2 * nf2], ah, bl0);     mma16816(S[2 * nf2 + 1], ah, bl1);
                mma16816(S[2 * nf2], al, bh0);     mma16816(S[2 * nf2 + 1], al, bh1);
            }
        }

        float mx0 = mrow0, mx1 = mrow1;
        #pragma unroll
        for (int f = 0; f < 16; f++) {
            int col = f * 8 + q2c;
            bool k0 = sel_s[col] > 0.5f, k1 = sel_s[col + 1] > 0.5f;
            S[f][0] = k0 ? S[f][0] * 0.125f : -1.0e9f;
            S[f][1] = k1 ? S[f][1] * 0.125f : -1.0e9f;
            S[f][2] = k0 ? S[f][2] * 0.125f : -1.0e9f;
            S[f][3] = k1 ? S[f][3] * 0.125f : -1.0e9f;
            mx0 = fmaxf(mx0, fmaxf(S[f][0], S[f][1]));
            mx1 = fmaxf(mx1, fmaxf(S[f][2], S[f][3]));
        }
        #pragma unroll
        for (int o = 1; o < 4; o <<= 1) {
            mx0 = fmaxf(mx0, __shfl_xor_sync(0xffffffffu, mx0, o));
            mx1 = fmaxf(mx1, __shfl_xor_sync(0xffffffffu, mx1, o));
        }
        const float sc0 = expf(mrow0 - mx0);
        const float sc1 = expf(mrow1 - mx1);
        mrow0 = mx0; mrow1 = mx1;
        lrow0 *= sc0; lrow1 *= sc1;
        #pragma unroll
        for (int f = 0; f < 8; f++) {
            O[f][0] *= sc0; O[f][1] *= sc0; O[f][2] *= sc1; O[f][3] *= sc1;
        }
        uint32_t P[8][4];
        float rs0 = 0.f, rs1 = 0.f;
        #pragma unroll
        for (int nf2 = 0; nf2 < 8; nf2++) {
            float p00 = expf(S[2 * nf2][0] - mx0),     p01 = expf(S[2 * nf2][1] - mx0);
            float p10 = expf(S[2 * nf2][2] - mx1),     p11 = expf(S[2 * nf2][3] - mx1);
            float p20 = expf(S[2 * nf2 + 1][0] - mx0), p21 = expf(S[2 * nf2 + 1][1] - mx0);
            float p30 = expf(S[2 * nf2 + 1][2] - mx1), p31 = expf(S[2 * nf2 + 1][3] - mx1);
            rs0 += p00 + p01 + p20 + p21;
            rs1 += p10 + p11 + p30 + p31;
            P[nf2][0] = packf2(p00, p01);
            P[nf2][1] = packf2(p10, p11);
            P[nf2][2] = packf2(p20, p21);
            P[nf2][3] = packf2(p30, p31);
        }
        #pragma unroll
        for (int o = 1; o < 4; o <<= 1) {
            rs0 += __shfl_xor_sync(0xffffffffu, rs0, o);
            rs1 += __shfl_xor_sync(0xffffffffu, rs1, o);
        }
        lrow0 += rs0; lrow1 += rs1;

        #pragma unroll
        for (int ks2 = 0; ks2 < 8; ks2++) {
            #pragma unroll
            for (int dn = 0; dn < 4; dn++) {
                uint32_t th[4], tl[4];
                ldsm4(th, sb + V0 + (uint32_t)((bRow + dn * 16) * VROWB + (ks2 * 16 + bKs) * 2));
                ldsm4(tl, sb + V0 + VPLB + (uint32_t)((bRow + dn * 16) * VROWB + (ks2 * 16 + bKs) * 2));
                uint32_t bh0[2] = {th[0], th[1]}, bh1[2] = {th[2], th[3]};
                uint32_t bl0[2] = {tl[0], tl[1]}, bl1[2] = {tl[2], tl[3]};
                mma16816(O[2 * dn],     P[ks2], bh0);
                mma16816(O[2 * dn + 1], P[ks2], bh1);
                mma16816(O[2 * dn],     P[ks2], bl0);
                mma16816(O[2 * dn + 1], P[ks2], bl1);
            }
        }
        __syncthreads();
    }

    const float li0 = 1.f / lrow0, li1 = 1.f / lrow1;
    const int row0 = m0 + wid * 16 + (lane >> 2);
    __nv_bfloat16* ob = o2 + (size_t)b * ND;
    #pragma unroll
    for (int f = 0; f < 8; f++) {
        int d = hc * DH + f * 8 + q2c;
        float v00 = O[f][0] * li0, v01 = O[f][1] * li0;
        float v10 = O[f][2] * li1, v11 = O[f][3] * li1;
        __nv_bfloat16 h00, l00, h01, l01, h10, l10, h11, l11;
        split1(v00, h00, l00); split1(v01, h01, l01);
        split1(v10, h10, l10); split1(v11, h11, l11);
        size_t o0 = (size_t)row0 * Dd + d;
        size_t o1 = (size_t)(row0 + 8) * Dd + d;
        *reinterpret_cast<uint32_t*>(ob + o0) = pack2(h00, h01);
        *reinterpret_cast<uint32_t*>(ob + o1) = pack2(h10, h11);
        *reinterpret_cast<uint32_t*>(ob + plane + o0) = pack2(l00, l01);
        *reinterpret_cast<uint32_t*>(ob + plane + o1) = pack2(l10, l11);
    }
}

// ---------------- auxiliary kernels ----------------
__global__ void k_posquery1(const float* __restrict__ x, const int* __restrict__ mask,
                            float* __restrict__ part, float* __restrict__ cntp)
{
    int seg = blockIdx.x, b = blockIdx.y, d = threadIdx.x;
    int n0 = seg * 64;
    float s = 0.f, cnt = 0.f;
    for (int n = n0; n < n0 + 64; n++) {
        if (mask[b * Nn + n] == 1) { s += x[((size_t)b * Nn + n) * Dd + d]; cnt += 1.f; }
    }
    part[((size_t)b * 16 + seg) * Dd + d] = s;
    if (d == 0) cntp[b * 16 + seg] = cnt;
}
__global__ void k_posquery2(const float* __restrict__ part, const float* __restrict__ cntp,
                            float* __restrict__ pq)
{
    int b = blockIdx.x, d = threadIdx.x;
    float s = 0.f, cnt = 0.f;
    #pragma unroll
    for (int seg = 0; seg < 16; seg++) {
        s += part[((size_t)b * 16 + seg) * Dd + d];
        cnt += cntp[b * 16 + seg];
    }
    pq[b * Dd + d] = s / fmaxf(cnt, 1.f);
}

__global__ void k_mv1(const float* __restrict__ Wq, const float* __restrict__ pq,
                      float* __restrict__ qs)
{
    __shared__ float spq[Dd];
    __shared__ float red[8][32];
    int b = blockIdx.y, t0 = blockIdx.x * 32;
    int tid = threadIdx.x;
    spq[tid] = pq[b * Dd + tid];
    __syncthreads();
    int tseg = tid >> 5, tl = tid & 31;
    float s = 0.f;
    #pragma unroll
    for (int i = 0; i < 32; i++)
        s += spq[tseg * 32 + i] * Wq[(tseg * 32 + i) * Dd + t0 + tl];
    red[tseg][tl] = s;
    __syncthreads();
    if (tseg == 0) {
        float a = 0.f;
        #pragma unroll
        for (int k = 0; k < 8; k++) a += red[k][tl];
        qs[b * Dd + t0 + tl] = a;
    }
}
__global__ void k_mv2(const float* __restrict__ Wx, const float* __restrict__ qs,
                      float* __restrict__ w)
{
    int b = blockIdx.y;
    int wid = threadIdx.x >> 5, lane = threadIdx.x & 31;
    int t = blockIdx.x * 8 + wid;
    float s = 0.f;
    #pragma unroll
    for (int k = 0; k < 8; k++)
        s += Wx[(size_t)t * Dd + lane + 32 * k] * qs[b * Dd + lane + 32 * k];
    #pragma unroll
    for (int o = 16; o; o >>= 1) s += __shfl_xor_sync(0xffffffffu, s, o);
    if (lane == 0) w[b * Dd + t] = s;
}

__global__ void k_possim(const float* __restrict__ x, const float* __restrict__ w,
                         float* __restrict__ possim_out, float* __restrict__ sel)
{
    int row = blockIdx.x * 8 + (threadIdx.x >> 5);
    int lane = threadIdx.x & 31;
    int b = row / Nn;
    const float4* xr = reinterpret_cast<const float4*>(x + (size_t)row * Dd);
    const float4* wr = reinterpret_cast<const float4*>(w + b * Dd);
    float s = 0.f;
    #pragma unroll
    for (int e = 0; e < 2; e++) {
        float4 xv = xr[lane + e * 32];
        float4 wv = wr[lane + e * 32];
        s += xv.x * wv.x + xv.y * wv.y + xv.z * wv.z + xv.w * wv.w;
    }
    #pragma unroll
    for (int o = 16; o; o >>= 1) s += __shfl_xor_sync(0xffffffffu, s, o);
    if (lane == 0) {
        float p = 1.f / (1.f + expf(-s * 0.0625f));
        possim_out[row] = p;
        sel[row] = (p > 0.97f) ? 1.f : 0.f;
    }
}

__global__ void k_dot2p(const __nv_bfloat16* __restrict__ rows, long plane,
                        const float* __restrict__ a1, const float* __restrict__ a2,
                        float* __restrict__ s1, float* __restrict__ s2, int nheads)
{
    int row = blockIdx.x * 8 + (threadIdx.x >> 5);
    int lane = threadIdx.x & 31;
    int head = (row / Nn) % nheads;
    const __nv_bfloat16* rp = rows + (size_t)row * Dd;
    const float* a1p = a1 + head * Dd;
    const float* a2p = a2 + head * Dd;
    float u = 0.f, v = 0.f;
    for (int e = lane; e < Dd; e += 32) {
        float rv = __bfloat162float(rp[e]) + __bfloat162float(rp[plane + e]);
        u += rv * a1p[e];
        v += rv * a2p[e];
    }
    #pragma unroll
    for (int o = 16; o; o >>= 1) {
        u += __shfl_xor_sync(0xffffffffu, u, o);
        v += __shfl_xor_sync(0xffffffffu, v, o);
    }
    if (lane == 0) { s1[row] = u; s2[row] = v; }
}

__global__ void k_softmax_gat(const float* __restrict__ s1, const float* __restrict__ s2,
                              const uint8_t* __restrict__ connect, __nv_bfloat16* __restrict__ attn,
                              int nheads)
{
    __shared__ float s2row[Nn];
    __shared__ float r8[8];
    int z = blockIdx.y;
    int b = z / nheads;
    int t = threadIdx.x;
    int wid = t >> 5, lane = t & 31;
    #pragma unroll
    for (int k = 0; k < 4; k++) s2row[t + k * 256] = s2[(size_t)z * Nn + t + k * 256];
    __syncthreads();
    #pragma unroll
    for (int r = 0; r < 4; r++) {
        int i = blockIdx.x * 4 + r;
        const uint8_t* con = connect + (size_t)b * NNt + (size_t)i * Nn;
        float s1v = s1[(size_t)z * Nn + i];
        float v[4];
        float mx = -INFINITY;
        #pragma unroll
        for (int k = 0; k < 4; k++) {
            int j = t + k * 256;
            float e = s1v + s2row[j];
            e = (e >= 0.f) ? e : 0.2f * e;
            v[k] = con[j] ? e : -9.0e15f;
            mx = fmaxf(mx, v[k]);
        }
        mx = bred<true>(mx, r8, wid, lane);
        float sum = 0.f;
        #pragma unroll
        for (int k = 0; k < 4; k++) { v[k] = expf(v[k] - mx); sum += v[k]; }
        sum = bred<false>(sum, r8, wid, lane);
        float inv = 1.f / sum;
        __nv_bfloat16* out = attn + (size_t)z * NNt + (size_t)i * Nn;
        #pragma unroll
        for (int k = 0; k < 4; k++) out[t + k * 256] = __float2bfloat16(v[k] * inv);
        __syncthreads();
    }
}

__global__ void k_ln(const float* __restrict__ in, const float* __restrict__ g,
                     const float* __restrict__ bb, __nv_bfloat16* __restrict__ out, long oplane)
{
    int row = blockIdx.x * 8 + (threadIdx.x >> 5);
    int lane = threadIdx.x & 31;
    size_t base = (size_t)row * Dd;
    float vbuf[8];
    float s = 0.f, sq = 0.f;
    #pragma unroll
    for (int k = 0; k < 8; k++) {
        float x = in[base + lane + k * 32];
        vbuf[k] = x; s += x; sq += x * x;
    }
    #pragma unroll
    for (int o = 16; o; o >>= 1) {
        s += __shfl_xor_sync(0xffffffffu, s, o);
        sq += __shfl_xor_sync(0xffffffffu, sq, o);
    }
    float mean = s * (1.f / Dd);
    float var = sq * (1.f / Dd) - mean * mean;
    float rstd = rsqrtf(var + 1e-5f);
    #pragma unroll
    for (int k = 0; k < 8; k++) {
        int d = lane + k * 32;
        float y = (vbuf[k] - mean) * rstd * g[d] + bb[d];
        __nv_bfloat16 h, l; split1(y, h, l);
        out[base + d] = h; out[oplane + base + d] = l;
    }
}

__global__ void k_qfull_ln(const __nv_bfloat16* __restrict__ gout, long gplane,
                           const float* __restrict__ pe,
                           const float* __restrict__ sel, const float* __restrict__ g,
                           const float* __restrict__ bb, __nv_bfloat16* __restrict__ out, long oplane)
{
    int row = blockIdx.x * 8 + (threadIdx.x >> 5);
    int lane = threadIdx.x & 31;
    int n = row % Nn;
    size_t base = (size_t)row * Dd;
    float selv = sel[row];
    float vbuf[8];
    float s = 0.f, sq = 0.f;
    #pragma unroll
    for (int k = 0; k < 8; k++) {
        int d = lane + k * 32;
        float gv = __bfloat162float(gout[base + d]) + __bfloat162float(gout[gplane + base + d]);
        float x = (selv > 0.5f) ? (gv + pe[(size_t)n * Dd + d]) : 0.f;
        vbuf[k] = x; s += x; sq += x * x;
    }
    #pragma unroll
    for (int o = 16; o; o >>= 1) {
        s += __shfl_xor_sync(0xffffffffu, s, o);
        sq += __shfl_xor_sync(0xffffffffu, sq, o);
    }
    float mean = s * (1.f / Dd);
    float var = sq * (1.f / Dd) - mean * mean;
    float rstd = rsqrtf(var + 1e-5f);
    #pragma unroll
    for (int k = 0; k < 8; k++) {
        int d = lane + k * 32;
        float y = (vbuf[k] - mean) * rstd * g[d] + bb[d];
        __nv_bfloat16 h, l; split1(y, h, l);
        out[base + d] = h; out[oplane + base + d] = l;
    }
}

// ---------------- launch ----------------
#define GETSYM(p, T, s) do { void* _t; cudaGetSymbolAddress(&_t, s); p = (T*)_t; } while (0)
#define SMEMSZ(BM, BN, NA, NB) ((2 * (NA) * (BM) + 2 * (NB) * (BN)) * ROWB)

extern "C" void kernel_launch(void* const* d_in, const int* in_sizes, int n_in,
                              void* d_out, int out_size)
{
    const float* x      = (const float*)d_in[0];
    const int*   mask   = (const int*)  d_in[1];
    const float* pe     = (const float*)d_in[2];
    const float* simWx  = (const float*)d_in[3];
    const float* simWq  = (const float*)d_in[4];
    const float* adjW   = (const float*)d_in[5];
    const float* gatW   = (const float*)d_in[6];
    const float* gatA1  = (const float*)d_in[7];
    const float* gatA2  = (const float*)d_in[8];
    const float* gatWo  = (const float*)d_in[9];
    const float* gatAo1 = (const float*)d_in[10];
    const float* gatAo2 = (const float*)d_in[11];
    const float* ln3g   = (const float*)d_in[12];
    const float* ln3b   = (const float*)d_in[13];
    const float* ln4g   = (const float*)d_in[14];
    const float* ln4b   = (const float*)d_in[15];
    const float* caWq   = (const float*)d_in[16];
    const float* caWk   = (const float*)d_in[17];
    const float* caWv   = (const float*)d_in[18];
    const float* caWp   = (const float*)d_in[19];
    const float* gamma  = (const float*)d_in[20];
    (void)in_sizes; (void)n_in; (void)out_size;

    float* out = (float*)d_out;
    float* possim_out = out + (size_t)Bz * Nn * Dd;

    float *posq, *pqpart, *pqcnt, *qsv, *w, *sel, *s1, *s2, *so1, *so2;
    uint8_t* connect;
    __nv_bfloat16 *attn_bf, *attno_bf;
    __nv_bfloat16 *x2, *fa2, *Wh2, *WhT2, *cat2, *Who2, *WhoT2, *gout2, *qx2, *kv2;
    __nv_bfloat16 *q2, *k2, *vT2, *o2;
    __nv_bfloat16 *adjWT2, *gatWT2, *WoT2, *caWqT2, *caWkT2, *caWvT2, *caWpT2;
    GETSYM(posq, float, g_posq);   GETSYM(pqpart, float, g_pqpart); GETSYM(pqcnt, float, g_pqcnt);
    GETSYM(qsv, float, g_qs);      GETSYM(w, float, g_w);       GETSYM(sel, float, g_sel);
    GETSYM(connect, uint8_t, g_connect);
    GETSYM(s1, float, g_s1);       GETSYM(s2, float, g_s2);
    GETSYM(so1, float, g_so1);     GETSYM(so2, float, g_so2);
    GETSYM(attn_bf, __nv_bfloat16, g_attn_bf);
    GETSYM(attno_bf, __nv_bfloat16, g_attno_bf);
    GETSYM(x2, __nv_bfloat16, g_x2);     GETSYM(fa2, __nv_bfloat16, g_fa2);
    GETSYM(Wh2, __nv_bfloat16, g_Wh2);   GETSYM(WhT2, __nv_bfloat16, g_WhT2);
    GETSYM(cat2, __nv_bfloat16, g_cat2);
    GETSYM(Who2, __nv_bfloat16, g_Who2); GETSYM(WhoT2, __nv_bfloat16, g_WhoT2);
    GETSYM(gout2, __nv_bfloat16, g_gout2);
    GETSYM(qx2, __nv_bfloat16, g_qx2);   GETSYM(kv2, __nv_bfloat16, g_kv2);
    GETSYM(q2, __nv_bfloat16, g_q2);     GETSYM(k2, __nv_bfloat16, g_k2);
    GETSYM(vT2, __nv_bfloat16, g_vT2);   GETSYM(o2, __nv_bfloat16, g_o2);
    GETSYM(adjWT2, __nv_bfloat16, g_adjWT2); GETSYM(gatWT2, __nv_bfloat16, g_gatWT2);
    GETSYM(WoT2, __nv_bfloat16, g_WoT2);
    GETSYM(caWqT2, __nv_bfloat16, g_caWqT2); GETSYM(caWkT2, __nv_bfloat16, g_caWkT2);
    GETSYM(caWvT2, __nv_bfloat16, g_caWvT2); GETSYM(caWpT2, __nv_bfloat16, g_caWpT2);

    const long PL_BND  = (long)Bz * ND;
    const long PL_BHND = (long)Bz * Hh * ND;
    const long PL_CAT  = (long)Bz * Nn * HD;
    const long PL_DD   = (long)Dd * Dd;
    const long PL_GATW = (long)Hh * Dd * Dd;
    const long PL_WO   = (long)HD * Dd;

    const int SM_M2_22 = SMEMSZ(64, 128, 2, 2);
    const int SM_M2_12 = SMEMSZ(64, 128, 1, 2);
    const int SM_M4_22 = SMEMSZ(128, 128, 2, 2);
    const int SM_M4_11 = SMEMSZ(128, 128, 1, 1);
    cudaFuncSetAttribute(mma_gemm<2,128,2,4,EPI_NONE,   2,2,OUT_PLANES, false>, cudaFuncAttributeMaxDynamicSharedMemorySize, SM_M2_22);
    cudaFuncSetAttribute(mma_gemm<2,128,2,4,EPI_NONE,   2,2,OUT_PLANES, true >, cudaFuncAttributeMaxDynamicSharedMemorySize, SM_M2_22);
    cudaFuncSetAttribute(mma_gemm<2,128,2,4,EPI_NONE,   2,2,OUT_NONE,   true >, cudaFuncAttributeMaxDynamicSharedMemorySize, SM_M2_22);
    cudaFuncSetAttribute(mma_gemm<2,128,2,4,EPI_RESID,  2,2,OUT_F32,    false>, cudaFuncAttributeMaxDynamicSharedMemorySize, SM_M2_22);
    cudaFuncSetAttribute(mma_gemm<2,128,2,4,EPI_ELU,    1,2,OUT_PLANES, false>, cudaFuncAttributeMaxDynamicSharedMemorySize, SM_M2_12);
    cudaFuncSetAttribute(mma_gemm<4,128,2,4,EPI_NONE,   2,2,OUT_PLANES, true >, cudaFuncAttributeMaxDynamicSharedMemorySize, SM_M4_22);
    cudaFuncSetAttribute(mma_gemm<4,128,2,4,EPI_CONNECT,2,2,OUT_CONNECT,false>, cudaFuncAttributeMaxDynamicSharedMemorySize, SM_M4_22);
    cudaFuncSetAttribute(mma_gemm<4,128,2,4,EPI_ELU,    1,1,OUT_PLANES, false>, cudaFuncAttributeMaxDynamicSharedMemorySize, SM_M4_11);
    cudaFuncSetAttribute(k_flash_ca, cudaFuncAttributeMaxDynamicSharedMemorySize, FCA_SMEM);

    const long zero = 0;
    cudaStream_t s0 = 0;
    cudaStream_t sA = hx.s1;
    cudaStream_t sB = hx.s2;

    // fork
    cudaEventRecord(hx.e0, s0);
    cudaStreamWaitEvent(sA, hx.e0, 0);
    cudaStreamWaitEvent(sB, hx.e0, 0);

    // stream B: weight transposes -> LN3 -> q projection
    k_transpose_all<<<1344, dim3(32, 8), 0, sB>>>(adjW, adjWT2, caWq, caWqT2, caWk, caWkT2,
                                                  caWv, caWvT2, caWp, caWpT2, gatW, gatWT2, gatWo, WoT2);
    cudaEventRecord(hx.eT, sB);
    k_ln<<<Bz * Nn / 8, 256, 0, sB>>>(x, ln3g, ln3b, qx2, PL_BND);

    // stream 0: split x
    k_split<<<Bz * ND / 1024, 256, 0, s0>>>(x, x2, PL_BND);
    cudaEventRecord(hx.eX, s0);

    // stream B: q = qx @ caWq
    mma_gemm<2,128,2,4,EPI_NONE,2,2,OUT_PLANES,false><<<dim3(2, 128, 1), 256, SM_M2_22, sB>>>(
        qx2, PL_BND, caWqT2, PL_DD, q2, PL_BND,
        Dd, Dd, Dd, Dd, 1, zero, zero, zero, zero, zero, zero,
        nullptr, zero, nullptr, nullptr, zero, zero, zero, 0);
    cudaEventRecord(hx.eQ, sB);

    // stream A: selection path, then fa -> connect (full precision)
    k_posquery1<<<dim3(16, Bz), 256, 0, sA>>>(x, mask, pqpart, pqcnt);
    k_posquery2<<<Bz, 256, 0, sA>>>(pqpart, pqcnt, posq);
    k_mv1<<<dim3(8, Bz), 256, 0, sA>>>(simWq, posq, qsv);
    k_mv2<<<dim3(32, Bz), 256, 0, sA>>>(simWx, qsv, w);
    k_possim<<<Bz * Nn / 8, 256, 0, sA>>>(x, w, possim_out, sel);
    cudaStreamWaitEvent(sA, hx.eX, 0);
    cudaStreamWaitEvent(sA, hx.eT, 0);
    mma_gemm<2,128,2,4,EPI_NONE,2,2,OUT_PLANES,false><<<dim3(2, 128, 1), 256, SM_M2_22, sA>>>(
        x2, PL_BND, adjWT2, PL_DD, fa2, PL_BND,
        Dd, Dd, Dd, Dd, 1, zero, zero, zero, zero, zero, zero,
        nullptr, zero, nullptr, nullptr, zero, zero, zero, 0);
    mma_gemm<4,128,2,4,EPI_CONNECT,2,2,OUT_CONNECT,false><<<dim3(8, 8, Bz), 256, SM_M4_22, sA>>>(
        fa2, PL_BND, fa2, PL_BND, connect, zero,
        Dd, Dd, Dd, Nn, 1, (long)ND, zero, (long)ND, zero, (long)NNt, zero,
        sel, (long)Nn, nullptr, nullptr, zero, zero, zero, 0);
    cudaEventRecord(hx.eConn, sA);

    // stream 0: main chain
    cudaStreamWaitEvent(s0, hx.eT, 0);

    mma_gemm<4,128,2,4,EPI_NONE,2,2,OUT_PLANES,true><<<dim3(2, 8, Bz * Hh), 256, SM_M4_22, s0>>>(
        x2, PL_BND, gatWT2, PL_GATW, Wh2, PL_BHND,
        Dd, Dd, Dd, Dd, Hh, (long)ND, zero, zero, (long)Dd * Dd,
        (long)Hh * ND, (long)ND,
        nullptr, zero, nullptr, WhT2, PL_BHND, (long)Hh * ND, (long)ND, Nn);

    k_dot2p<<<Bz * Hh * Nn / 8, 256, 0, s0>>>(Wh2, PL_BHND, gatA1, gatA2, s1, s2, Hh);

    cudaStreamWaitEvent(s0, hx.eConn, 0);
    k_softmax_gat<<<dim3(Nn / 4, Bz * Hh), 256, 0, s0>>>(s1, s2, connect, attn_bf, Hh);

    // cat = elu( attn @ Wh )  [1 product: P_hi x Wh_hi — the one retained cut]
    mma_gemm<4,128,2,4,EPI_ELU,1,1,OUT_PLANES,false><<<dim3(2, 8, Bz * Hh), 256, SM_M4_11, s0>>>(
        attn_bf, zero, WhT2, PL_BHND, cat2, PL_CAT,
        Nn, Nn, Nn, HD, Hh, (long)Hh * NNt, (long)NNt, (long)Hh * ND, (long)ND,
        (long)Nn * HD, (long)Dd,
        nullptr, zero, nullptr, nullptr, zero, zero, zero, 0);

    // Who: full 3-product (R12 numerics)
    mma_gemm<2,128,2,4,EPI_NONE,2,2,OUT_PLANES,true><<<dim3(2, 16, Bz), 256, SM_M2_22, s0>>>(
        cat2, PL_CAT, WoT2, PL_WO, Who2, PL_BND,
        HD, HD, HD, Dd, 1, (long)Nn * HD, zero, zero, zero, (long)ND, zero,
        nullptr, zero, nullptr, WhoT2, PL_BND, (long)ND, zero, Nn);

    k_dot2p<<<Bz * Nn / 8, 256, 0, s0>>>(Who2, PL_BND, gatAo1, gatAo2, so1, so2, 1);
    k_softmax_gat<<<dim3(Nn / 4, Bz), 256, 0, s0>>>(so1, so2, connect, attno_bf, 1);

    // gout = elu( attn_o @ Who )  [2 products, R12 numerics]
    mma_gemm<2,128,2,4,EPI_ELU,1,2,OUT_PLANES,false><<<dim3(2, 16, Bz), 256, SM_M2_12, s0>>>(
        attno_bf, zero, WhoT2, PL_BND, gout2, PL_BND,
        Nn, Nn, Nn, Dd, 1, (long)NNt, zero, (long)ND, zero, (long)ND, zero,
        nullptr, zero, nullptr, nullptr, zero, zero, zero, 0);

    k_qfull_ln<<<Bz * Nn / 8, 256, 0, s0>>>(gout2, PL_BND, pe, sel, ln4g, ln4b, kv2, PL_BND);
    cudaEventRecord(hx.eKV, s0);

    // stream B: k projection (parallel with vT on s0)
    cudaStreamWaitEvent(sB, hx.eKV, 0);
    mma_gemm<2,128,2,4,EPI_NONE,2,2,OUT_PLANES,false><<<dim3(2, 128, 1), 256, SM_M2_22, sB>>>(
        kv2, PL_BND, caWkT2, PL_DD, k2, PL_BND,
        Dd, Dd, Dd, Dd, 1, zero, zero, zero, zero, zero, zero,
        nullptr, zero, nullptr, nullptr, zero, zero, zero, 0);
    cudaEventRecord(hx.eK, sB);

    // stream 0: v projection (transposed planes only)
    mma_gemm<2,128,2,4,EPI_NONE,2,2,OUT_NONE,true><<<dim3(2, 16, Bz), 256, SM_M2_22, s0>>>(
        kv2, PL_BND, caWvT2, PL_DD, nullptr, zero,
        Dd, Dd, Dd, Dd, 1, (long)ND, zero, zero, zero, (long)ND, zero,
        nullptr, zero, nullptr, vT2, PL_BND, (long)ND, zero, Nn);

    // fused flash CA (V plane-pair, R12 numerics)
    cudaStreamWaitEvent(s0, hx.eQ, 0);
    cudaStreamWaitEvent(s0, hx.eK, 0);
    k_flash_ca<<<dim3(Nn / 128, Bz * HC), 256, FCA_SMEM, s0>>>(
        q2, k2, vT2, sel, o2, PL_BND);

    // out = x + gamma * (o @ caWp)
    mma_gemm<2,128,2,4,EPI_RESID,2,2,OUT_F32,false><<<dim3(2, 128, 1), 256, SM_M2_22, s0>>>(
        o2, PL_BND, caWpT2, PL_DD, out, zero,
        Dd, Dd, Dd, Dd, 1, zero, zero, zero, zero, zero, zero,
        x, zero, gamma, nullptr, zero, zero, zero, 0);
}

// round 15
// speedup vs baseline: 1.1811x; 1.0774x over previous
#include <cuda_runtime.h>
#include <cuda_bf16.h>
#include <math.h>
#include <stdint.h>

// Problem constants
#define Bz 8
#define Nn 1024
#define Dd 256
#define Hh 8
#define HC 4
#define DH 64
#define HD 2048                 // Hh*Dd
#define ND (Nn*Dd)              // 262144
#define NNt ((size_t)Nn*Nn)     // 1048576

// ---------------- scratch (device globals) ----------------
__device__ float g_posq[Bz*Dd];
__device__ float g_pqpart[Bz*16*Dd];
__device__ float g_pqcnt[Bz*16];
__device__ float g_qs[Bz*Dd];
__device__ float g_w[Bz*Dd];
__device__ float g_sel[Bz*Nn];
__device__ uint8_t g_connect[(size_t)Bz*Nn*Nn];
__device__ float g_s1[Bz*Hh*Nn];
__device__ float g_s2[Bz*Hh*Nn];
__device__ float g_so1[Bz*Nn];
__device__ float g_so2[Bz*Nn];
__device__ __nv_bfloat16 g_attn_bf[(size_t)Bz*Hh*Nn*Nn];   // GAT probs
__device__ __nv_bfloat16 g_attno_bf[(size_t)Bz*Nn*Nn];

__device__ __nv_bfloat16 g_x2[2*(size_t)Bz*ND];
__device__ __nv_bfloat16 g_fa2[2*(size_t)Bz*ND];
__device__ __nv_bfloat16 g_WhT2[2*(size_t)Bz*Hh*ND];   // hi plane only used
__device__ __nv_bfloat16 g_cat2[2*(size_t)Bz*Nn*HD];
__device__ __nv_bfloat16 g_WhoT2[2*(size_t)Bz*ND];
__device__ __nv_bfloat16 g_gout2[2*(size_t)Bz*ND];
__device__ __nv_bfloat16 g_qx2[2*(size_t)Bz*ND];
__device__ __nv_bfloat16 g_kv2[2*(size_t)Bz*ND];
__device__ __nv_bfloat16 g_q2[2*(size_t)Bz*ND];
__device__ __nv_bfloat16 g_k2[2*(size_t)Bz*ND];
__device__ __nv_bfloat16 g_vT2[2*(size_t)Bz*ND];
__device__ __nv_bfloat16 g_o2[2*(size_t)Bz*ND];
// transposed weights (planes)
__device__ __nv_bfloat16 g_adjWT2[2*Dd*Dd];
__device__ __nv_bfloat16 g_gatWT2[2*Hh*Dd*Dd];
__device__ __nv_bfloat16 g_WoT2[2*HD*Dd];
__device__ __nv_bfloat16 g_caWqT2[2*Dd*Dd];
__device__ __nv_bfloat16 g_caWkT2[2*Dd*Dd];
__device__ __nv_bfloat16 g_caWvT2[2*Dd*Dd];
__device__ __nv_bfloat16 g_caWpT2[2*Dd*Dd];

// ---------------- streams/events ----------------
struct HXStreams {
    cudaStream_t s1, s2;
    cudaEvent_t e0, eT, eX, eConn, eQ, eKV, eK;
    HXStreams() {
        cudaStreamCreateWithFlags(&s1, cudaStreamNonBlocking);
        cudaStreamCreateWithFlags(&s2, cudaStreamNonBlocking);
        cudaEventCreateWithFlags(&e0, cudaEventDisableTiming);
        cudaEventCreateWithFlags(&eT, cudaEventDisableTiming);
        cudaEventCreateWithFlags(&eX, cudaEventDisableTiming);
        cudaEventCreateWithFlags(&eConn, cudaEventDisableTiming);
        cudaEventCreateWithFlags(&eQ, cudaEventDisableTiming);
        cudaEventCreateWithFlags(&eKV, cudaEventDisableTiming);
        cudaEventCreateWithFlags(&eK, cudaEventDisableTiming);
    }
};
static HXStreams hx;

// ---------------- low-level helpers ----------------
__device__ __forceinline__ uint32_t smem_u32(const void* p) {
    uint32_t a;
    asm("{ .reg .u64 t; cvta.to.shared.u64 t, %1; cvt.u32.u64 %0, t; }" : "=r"(a) : "l"(p));
    return a;
}
__device__ __forceinline__ void ldsm4(uint32_t* r, uint32_t addr) {
    asm volatile("ldmatrix.sync.aligned.m8n8.x4.shared.b16 {%0,%1,%2,%3}, [%4];"
        : "=r"(r[0]), "=r"(r[1]), "=r"(r[2]), "=r"(r[3]) : "r"(addr));
}
__device__ __forceinline__ void mma16816(float* c, const uint32_t* a, const uint32_t* b) {
    asm volatile("mma.sync.aligned.m16n8k16.row.col.f32.bf16.bf16.f32 "
        "{%0,%1,%2,%3}, {%4,%5,%6,%7}, {%8,%9}, {%0,%1,%2,%3};"
        : "+f"(c[0]), "+f"(c[1]), "+f"(c[2]), "+f"(c[3])
        : "r"(a[0]), "r"(a[1]), "r"(a[2]), "r"(a[3]), "r"(b[0]), "r"(b[1]));
}
__device__ __forceinline__ void split1(float v, __nv_bfloat16& h, __nv_bfloat16& l) {
    h = __float2bfloat16(v);
    l = __float2bfloat16(v - __bfloat162float(h));
}
__device__ __forceinline__ uint32_t pack2(__nv_bfloat16 a, __nv_bfloat16 b) {
    return (uint32_t)__bfloat16_as_ushort(a) | ((uint32_t)__bfloat16_as_ushort(b) << 16);
}
__device__ __forceinline__ uint32_t packf2(float a, float b) {
    uint32_t r;
    asm("cvt.rn.bf16x2.f32 %0, %1, %2;" : "=r"(r) : "f"(b), "f"(a));
    return r;
}
#define CP16(dst, src) \
    asm volatile("cp.async.cg.shared.global [%0], [%1], 16;" :: "r"(dst), "l"(src))
#define CP_COMMIT() asm volatile("cp.async.commit_group;" ::: "memory")

template <bool MAX>
__device__ __forceinline__ float bred(float v, float* r8, int wid, int lane) {
    #pragma unroll
    for (int o = 16; o; o >>= 1) {
        float u = __shfl_xor_sync(0xffffffffu, v, o);
        v = MAX ? fmaxf(v, u) : (v + u);
    }
    if (lane == 0) r8[wid] = v;
    __syncthreads();
    if (wid == 0) {
        float u = r8[lane & 7];
        #pragma unroll
        for (int o = 4; o; o >>= 1) {
            float t = __shfl_xor_sync(0xffffffffu, u, o);
            u = MAX ? fmaxf(u, t) : (u + t);
        }
        if (lane == 0) r8[0] = u;
    }
    __syncthreads();
    return r8[0];
}

// ---------------- split x into planes ----------------
__global__ void k_split(const float* __restrict__ in, __nv_bfloat16* __restrict__ outp, long plane)
{
    int i = blockIdx.x * 256 + threadIdx.x;
    float4 v = reinterpret_cast<const float4*>(in)[i];
    __nv_bfloat16 h0, l0, h1, l1, h2, l2, h3, l3;
    split1(v.x, h0, l0); split1(v.y, h1, l1); split1(v.z, h2, l2); split1(v.w, h3, l3);
    reinterpret_cast<uint2*>(outp)[i] = make_uint2(pack2(h0, h1), pack2(h2, h3));
    reinterpret_cast<uint2*>(outp + plane)[i] = make_uint2(pack2(l0, l1), pack2(l2, l3));
}

// ---------------- merged transpose kernel ----------------
__global__ void k_transpose_all(const float* adjW, __nv_bfloat16* adjWT,
                                const float* caWq, __nv_bfloat16* caWqT,
                                const float* caWk, __nv_bfloat16* caWkT,
                                const float* caWv, __nv_bfloat16* caWvT,
                                const float* caWp, __nv_bfloat16* caWpT,
                                const float* gatW, __nv_bfloat16* gatWT,
                                const float* gatWo, __nv_bfloat16* WoT)
{
    __shared__ float t[32][33];
    int id = blockIdx.x;
    int tx = threadIdx.x, ty = threadIdx.y;
    const float* src; __nv_bfloat16* dh; long plane; int R, C, bx, by;
    if (id < 320) {
        const float* srcs[5] = {adjW, caWq, caWk, caWv, caWp};
        __nv_bfloat16* dsts[5] = {adjWT, caWqT, caWkT, caWvT, caWpT};
        int m = id >> 6, l = id & 63;
        src = srcs[m]; dh = dsts[m]; plane = Dd * Dd;
        R = Dd; C = Dd; bx = (l & 7) * 32; by = (l >> 3) * 32;
    } else if (id < 832) {
        int l = id - 320; int z = l >> 6; l &= 63;
        src = gatW + (size_t)z * Dd * Dd; dh = gatWT + (size_t)z * Dd * Dd;
        plane = (long)Hh * Dd * Dd;
        R = Dd; C = Dd; bx = (l & 7) * 32; by = (l >> 3) * 32;
    } else {
        int l = id - 832;
        src = gatWo; dh = WoT; plane = (long)HD * Dd;
        R = HD; C = Dd; bx = (l & 7) * 32; by = (l >> 3) * 32;
    }
    #pragma unroll
    for (int i = 0; i < 32; i += 8)
        t[ty + i][tx] = src[(size_t)(by + ty + i) * C + bx + tx];
    __syncthreads();
    #pragma unroll
    for (int i = 0; i < 32; i += 8) {
        float v = t[tx][ty + i];
        __nv_bfloat16 h, l2;
        split1(v, h, l2);
        size_t o = (size_t)(bx + ty + i) * R + by + tx;
        dh[o] = h; dh[plane + o] = l2;
    }
}

// ---------------- plane-pair bf16 mma.sync NT GEMM ----------------
// BM = WM * MF * 16. NA/NB = A/B planes. DLO: write lo plane in DUAL.
// DOT: epilogue computes s1/s2 dots (Cv = s1 base, cPlane = s2 offset; e1/e2 = a1/a2, sE1b = per-zi stride)
enum { EPI_NONE = 0, EPI_ELU = 1, EPI_CONNECT = 2, EPI_RESID = 3 };
enum { OUT_F32 = 0, OUT_PLANES = 1, OUT_CONNECT = 2, OUT_NONE = 3 };
#define ROWB 80

template <int MF, int BN, int WM, int WN, int EPI, int NA, int NB, int OUT, bool DUAL, bool DLO, int DOT>
__global__ void __launch_bounds__(256, 2)
mma_gemm(const __nv_bfloat16* __restrict__ A, long aPlane,
         const __nv_bfloat16* __restrict__ Bm, long bPlane,
         void* __restrict__ Cv, long cPlane,
         int K, int lda, int ldb, int ldc, int zInner,
         long sAb, long sAi, long sBb, long sBi, long sCb, long sCi,
         const float* __restrict__ e1, long sE1b, const float* __restrict__ e2,
         __nv_bfloat16* __restrict__ Ct, long ctPlane, long sCtb, long sCti, int ldct)
{
    constexpr int BM = WM * MF * 16;
    constexpr int ABYTES = BM * ROWB;
    constexpr int BBYTES = BN * ROWB;
    constexpr int STR = BM + 8;
    constexpr int STGPL = BN * STR;

    extern __shared__ char smem[];
    const uint32_t sb = smem_u32(smem);

    const int tid = threadIdx.x;
    const int wid = tid >> 5;
    const int lane = tid & 31;

    const int z = blockIdx.z;
    const int zb = z / zInner, zi = z % zInner;
    const __nv_bfloat16* Ap = A + (size_t)zb * sAb + (size_t)zi * sAi;
    const __nv_bfloat16* Bp = Bm + (size_t)zb * sBb + (size_t)zi * sBi;
    float* Cpf = (float*)Cv + (size_t)zb * sCb + (size_t)zi * sCi;
    __nv_bfloat16* Cpb = (__nv_bfloat16*)Cv + (size_t)zb * sCb + (size_t)zi * sCi;
    uint8_t* Cp8 = (uint8_t*)Cv + (size_t)zb * sCb + (size_t)zi * sCi;
    const float* e1p = e1 ? (e1 + (size_t)zb * sE1b) : nullptr;

    const int m0 = blockIdx.y * BM;
    const int n0 = blockIdx.x * BN;

    const int crow = tid >> 2;
    const int cch = tid & 3;

    const int wid_m = wid % WM;
    const int wid_n = wid / WM;
    const int g = lane >> 3, rl = lane & 7;
    const int aRowBase = wid_m * (MF * 16) + (g & 1) * 8 + rl;
    const int aKsel = (g >> 1) * 8;
    const int bRowBase = wid_n * 32 + (g >> 1) * 8 + rl;
    const int bKsel = (g & 1) * 8;

    float acc[MF][4][4] = {};
    const int nkt = K >> 5;
    const uint32_t bbase = 2 * NA * ABYTES;

    auto copyTile = [&](int kk, int stage) {
        #pragma unroll
        for (int pl = 0; pl < NA; pl++) {
            const __nv_bfloat16* src = Ap + (size_t)pl * aPlane;
            uint32_t dst0 = sb + (stage * NA + pl) * ABYTES;
            #pragma unroll
            for (int i = 0; i < BM / 64; i++) {
                int row = crow + 64 * i;
                CP16(dst0 + row * ROWB + cch * 16,
                     src + (size_t)(m0 + row) * lda + kk + cch * 8);
            }
        }
        #pragma unroll
        for (int pl = 0; pl < NB; pl++) {
            const __nv_bfloat16* src = Bp + (size_t)pl * bPlane;
            uint32_t dst0 = sb + bbase + (stage * NB + pl) * BBYTES;
            #pragma unroll
            for (int i = 0; i < BN / 64; i++) {
                int row = crow + 64 * i;
                CP16(dst0 + row * ROWB + cch * 16,
                     src + (size_t)(n0 + row) * ldb + kk + cch * 8);
            }
        }
    };

    copyTile(0, 0); CP_COMMIT();

    for (int kt = 0; kt < nkt; kt++) {
        const int stage = kt & 1;
        const bool more = (kt + 1 < nkt);
        if (more) { copyTile((kt + 1) << 5, (kt + 1) & 1); CP_COMMIT(); }
        if (more) asm volatile("cp.async.wait_group 1;" ::: "memory");
        else      asm volatile("cp.async.wait_group 0;" ::: "memory");
        __syncthreads();

        const uint32_t sAhi = sb + stage * NA * ABYTES;
        const uint32_t sAlo = sAhi + ABYTES;
        const uint32_t sBhi = sb + bbase + stage * NB * BBYTES;
        const uint32_t sBlo = sBhi + BBYTES;

        #pragma unroll
        for (int j = 0; j < 2; j++) {
            const int kb = j * 16;
            uint32_t a[MF][4], bh[4][2], bl[4][2];
            #pragma unroll
            for (int im = 0; im < MF; im++)
                ldsm4(a[im], sAhi + (uint32_t)((aRowBase + im * 16) * ROWB + (kb + aKsel) * 2));
            #pragma unroll
            for (int i2 = 0; i2 < 2; i2++) {
                uint32_t t[4];
                ldsm4(t, sBhi + (uint32_t)((bRowBase + i2 * 16) * ROWB + (kb + bKsel) * 2));
                bh[2 * i2][0] = t[0]; bh[2 * i2][1] = t[1];
                bh[2 * i2 + 1][0] = t[2]; bh[2 * i2 + 1][1] = t[3];
            }
            #pragma unroll
            for (int im = 0; im < MF; im++)
                #pragma unroll
                for (int in = 0; in < 4; in++)
                    mma16816(acc[im][in], a[im], bh[in]);           // Ah*Bh
            if (NB == 2) {
                #pragma unroll
                for (int i2 = 0; i2 < 2; i2++) {
                    uint32_t t[4];
                    ldsm4(t, sBlo + (uint32_t)((bRowBase + i2 * 16) * ROWB + (kb + bKsel) * 2));
                    bl[2 * i2][0] = t[0]; bl[2 * i2][1] = t[1];
                    bl[2 * i2 + 1][0] = t[2]; bl[2 * i2 + 1][1] = t[3];
                }
                #pragma unroll
                for (int im = 0; im < MF; im++)
                    #pragma unroll
                    for (int in = 0; in < 4; in++)
                        mma16816(acc[im][in], a[im], bl[in]);       // Ah*Bl
            }
            if (NA == 2) {
                #pragma unroll
                for (int im = 0; im < MF; im++)
                    ldsm4(a[im], sAlo + (uint32_t)((aRowBase + im * 16) * ROWB + (kb + aKsel) * 2));
                #pragma unroll
                for (int im = 0; im < MF; im++)
                    #pragma unroll
                    for (int in = 0; in < 4; in++)
                        mma16816(acc[im][in], a[im], bh[in]);       // Al*Bh
            }
        }
        __syncthreads();
    }

    // epilogue
    __nv_bfloat16* stg = reinterpret_cast<__nv_bfloat16*>(smem);
    const int mw = m0 + wid_m * (MF * 16);
    const int nw = n0 + wid_n * 32;

    if (DOT) {
        // s1/s2 partial dots: s1 base = Cv + z*Nn ; s2 = s1 + cPlane
        float* s1p = (float*)Cv + (size_t)z * Nn;
        float* s2p = s1p + cPlane;
        const float* a1p = e1 + (size_t)zi * sE1b;
        const float* a2p = e2 + (size_t)zi * sE1b;
        #pragma unroll
        for (int im = 0; im < MF; im++) {
            const int row = mw + im * 16 + (lane >> 2);
            float d10 = 0.f, d20 = 0.f, d11 = 0.f, d21 = 0.f;
            #pragma unroll
            for (int in = 0; in < 4; in++) {
                const int col = nw + in * 8 + (lane & 3) * 2;
                float a10 = a1p[col], a11 = a1p[col + 1];
                float a20 = a2p[col], a21 = a2p[col + 1];
                d10 += acc[im][in][0] * a10 + acc[im][in][1] * a11;
                d20 += acc[im][in][0] * a20 + acc[im][in][1] * a21;
                d11 += acc[im][in][2] * a10 + acc[im][in][3] * a11;
                d21 += acc[im][in][2] * a20 + acc[im][in][3] * a21;
            }
            #pragma unroll
            for (int o = 1; o < 4; o <<= 1) {
                d10 += __shfl_xor_sync(0xffffffffu, d10, o);
                d20 += __shfl_xor_sync(0xffffffffu, d20, o);
                d11 += __shfl_xor_sync(0xffffffffu, d11, o);
                d21 += __shfl_xor_sync(0xffffffffu, d21, o);
            }
            if ((lane & 3) == 0) {
                atomicAdd(&s1p[row], d10);
                atomicAdd(&s2p[row], d20);
                atomicAdd(&s1p[row + 8], d11);
                atomicAdd(&s2p[row + 8], d21);
            }
        }
    }

    #pragma unroll
    for (int im = 0; im < MF; im++) {
        const int row = mw + im * 16 + (lane >> 2);
        const float sr0 = (EPI == EPI_CONNECT) ? e1p[row] : 0.f;
        const float sr1 = (EPI == EPI_CONNECT) ? e1p[row + 8] : 0.f;
        #pragma unroll
        for (int in = 0; in < 4; in++) {
            const int col = nw + in * 8 + (lane & 3) * 2;
            float v00 = acc[im][in][0], v01 = acc[im][in][1];
            float v10 = acc[im][in][2], v11 = acc[im][in][3];
            if (EPI == EPI_ELU) {
                v00 = v00 > 0.f ? v00 : expm1f(v00);
                v01 = v01 > 0.f ? v01 : expm1f(v01);
                v10 = v10 > 0.f ? v10 : expm1f(v10);
                v11 = v11 > 0.f ? v11 : expm1f(v11);
            } else if (EPI == EPI_RESID) {
                const float g0 = e2[col], g1 = e2[col + 1];
                const size_t r0 = (size_t)row * ldc + col;
                const size_t r1 = (size_t)(row + 8) * ldc + col;
                v00 = e1p[r0] + g0 * v00; v01 = e1p[r0 + 1] + g1 * v01;
                v10 = e1p[r1] + g0 * v10; v11 = e1p[r1 + 1] + g1 * v11;
            }
            const size_t o0 = (size_t)row * ldc + col;
            const size_t o1 = (size_t)(row + 8) * ldc + col;
            if (OUT == OUT_CONNECT) {
                const float sc0 = e1p[col], sc1 = e1p[col + 1];
                uchar2 c0, c1;
                c0.x = (v00 > 0.f && sr0 > 0.5f && sc0 > 0.5f) ? 1 : 0;
                c0.y = (v01 > 0.f && sr0 > 0.5f && sc1 > 0.5f) ? 1 : 0;
                c1.x = (v10 > 0.f && sr1 > 0.5f && sc0 > 0.5f) ? 1 : 0;
                c1.y = (v11 > 0.f && sr1 > 0.5f && sc1 > 0.5f) ? 1 : 0;
                *reinterpret_cast<uchar2*>(Cp8 + o0) = c0;
                *reinterpret_cast<uchar2*>(Cp8 + o1) = c1;
            } else if (OUT == OUT_F32) {
                *reinterpret_cast<float2*>(Cpf + o0) = make_float2(v00, v01);
                *reinterpret_cast<float2*>(Cpf + o1) = make_float2(v10, v11);
            }
            __nv_bfloat16 h00, l00, h01, l01, h10, l10, h11, l11;
            if (OUT == OUT_PLANES || DUAL) {
                split1(v00, h00, l00); split1(v01, h01, l01);
                split1(v10, h10, l10); split1(v11, h11, l11);
            }
            if (OUT == OUT_PLANES) {
                *reinterpret_cast<uint32_t*>(Cpb + o0) = pack2(h00, h01);
                *reinterpret_cast<uint32_t*>(Cpb + o1) = pack2(h10, h11);
                *reinterpret_cast<uint32_t*>(Cpb + cPlane + o0) = pack2(l00, l01);
                *reinterpret_cast<uint32_t*>(Cpb + cPlane + o1) = pack2(l10, l11);
            }
            if (DUAL) {
                const int cl = col - n0, rlc = row - m0;
                stg[cl * STR + rlc] = h00;
                stg[(cl + 1) * STR + rlc] = h01;
                stg[cl * STR + rlc + 8] = h10;
                stg[(cl + 1) * STR + rlc + 8] = h11;
                if (DLO) {
                    stg[STGPL + cl * STR + rlc] = l00;
                    stg[STGPL + (cl + 1) * STR + rlc] = l01;
                    stg[STGPL + cl * STR + rlc + 8] = l10;
                    stg[STGPL + (cl + 1) * STR + rlc + 8] = l11;
                }
            }
        }
    }
    if (DUAL) {
        __syncthreads();
        __nv_bfloat16* Ctp = Ct + (size_t)zb * sCtb + (size_t)zi * sCti;
        const int r = tid >> 1;
        const int hh = (tid & 1) * (BM / 2);
        #pragma unroll
        for (int p = 0; p < (DLO ? 2 : 1); p++) {
            const uint4* srow = reinterpret_cast<const uint4*>(stg + p * STGPL + r * STR + hh);
            uint4* drow = reinterpret_cast<uint4*>(Ctp + (size_t)p * ctPlane + (size_t)(n0 + r) * ldct + m0 + hh);
            #pragma unroll
            for (int i = 0; i < BM / 16; i++)
                drow[i] = srow[i];
        }
    }
}

// ---------------- fused flash cross-attention ----------------
#define QROWB 144
#define VROWB 272
#define QPLB (128*QROWB)
#define VPLB (64*VROWB)
#define FCA_SMEM (4*QPLB + 2*VPLB + 512)

__global__ void __launch_bounds__(256, 1)
k_flash_ca(const __nv_bfloat16* __restrict__ q2, const __nv_bfloat16* __restrict__ k2,
           const __nv_bfloat16* __restrict__ vT2, const float* __restrict__ sel,
           __nv_bfloat16* __restrict__ o2, long plane)
{
    extern __shared__ char smem[];
    const uint32_t sb = smem_u32(smem);
    const uint32_t Q0 = 0, K0 = 2 * QPLB, V0 = 4 * QPLB, SEL0 = 4 * QPLB + 2 * VPLB;
    const float* sel_s = reinterpret_cast<const float*>(smem + SEL0);

    const int tid = threadIdx.x, wid = tid >> 5, lane = tid & 31;
    const int b = blockIdx.y / HC, hc = blockIdx.y % HC;
    const int m0 = blockIdx.x * 128;

    const __nv_bfloat16* Qp = q2 + (size_t)b * ND + hc * DH;
    const __nv_bfloat16* Kp = k2 + (size_t)b * ND + hc * DH;
    const __nv_bfloat16* Vp = vT2 + (size_t)b * ND + (size_t)hc * DH * Nn;
    const float* selb = sel + b * Nn;

    {
        int row = tid >> 1, cb = (tid & 1) * 4;
        #pragma unroll
        for (int pl = 0; pl < 2; pl++)
            #pragma unroll
            for (int c = 0; c < 4; c++)
                CP16(sb + Q0 + pl * QPLB + row * QROWB + (cb + c) * 16,
                     Qp + (size_t)pl * plane + (size_t)(m0 + row) * Dd + (cb + c) * 8);
    }

    const int g = lane >> 3, rl = lane & 7;
    const int aRow = wid * 16 + (g & 1) * 8 + rl;
    const int aKs = (g >> 1) * 8;
    const int bRow = (g >> 1) * 8 + rl;
    const int bKs = (g & 1) * 8;
    const int q2c = (lane & 3) * 2;

    float O[8][4] = {};
    float mrow0 = -INFINITY, mrow1 = -INFINITY;
    float lrow0 = 0.f, lrow1 = 0.f;

    for (int kt = 0; kt < 8; kt++) {
        const int t0 = kt * 128;
        {
            int row = tid >> 1, cb = (tid & 1) * 4;
            #pragma unroll
            for (int pl = 0; pl < 2; pl++)
                #pragma unroll
                for (int c = 0; c < 4; c++)
                    CP16(sb + K0 + pl * QPLB + row * QROWB + (cb + c) * 16,
                         Kp + (size_t)pl * plane + (size_t)(t0 + row) * Dd + (cb + c) * 8);
            int vrow = tid >> 2, vcb = (tid & 3) * 4;
            #pragma unroll
            for (int pl = 0; pl < 2; pl++)
                #pragma unroll
                for (int c = 0; c < 4; c++)
                    CP16(sb + V0 + pl * VPLB + vrow * VROWB + (vcb + c) * 16,
                         Vp + (size_t)pl * plane + (size_t)vrow * Nn + t0 + (vcb + c) * 8);
            if (tid < 32)
                CP16(sb + SEL0 + tid * 16, selb + t0 + tid * 4);
        }
        CP_COMMIT();
        asm volatile("cp.async.wait_group 0;" ::: "memory");
        __syncthreads();

        float S[16][4];
        #pragma unroll
        for (int f = 0; f < 16; f++) { S[f][0] = S[f][1] = S[f][2] = S[f][3] = 0.f; }
        #pragma unroll
        for (int ks = 0; ks < 4; ks++) {
            uint32_t ah[4], al[4];
            ldsm4(ah, sb + Q0 + (uint32_t)(aRow * QROWB + (ks * 16 + aKs) * 2));
            ldsm4(al, sb + Q0 + QPLB + (uint32_t)(aRow * QROWB + (ks * 16 + aKs) * 2));
            #pragma unroll
            for (int nf2 = 0; nf2 < 8; nf2++) {
                uint32_t th[4], tl[4];
                ldsm4(th, sb + K0 + (uint32_t)((bRow + nf2 * 16) * QROWB + (ks * 16 + bKs) * 2));
                ldsm4(tl, sb + K0 + QPLB + (uint32_t)((bRow + nf2 * 16) * QROWB + (ks * 16 + bKs) * 2));
                uint32_t bh0[2] = {th[0], th[1]}, bh1[2] = {th[2], th[3]};
                uint32_t bl0[2] = {tl[0], tl[1]}, bl1[2] = {tl[2], tl[3]};
                mma16816(S[2 * nf2], ah, bh0);     mma16816(S[2 * nf2 + 1], ah, bh1);
                mma16816(S[2 * nf2], ah, bl0);     mma16816(S[2 * nf2 + 1], ah, bl1);
                mma16816(S[2 * nf2], al, bh0);     mma16816(S[2 * nf2 + 1], al, bh1);
            }
        }

        float mx0 = mrow0, mx1 = mrow1;
        #pragma unroll
        for (int f = 0; f < 16; f++) {
            int col = f * 8 + q2c;
            bool k0 = sel_s[col] > 0.5f, k1 = sel_s[col + 1] > 0.5f;
            S[f][0] = k0 ? S[f][0] * 0.125f : -1.0e9f;
            S[f][1] = k1 ? S[f][1] * 0.125f : -1.0e9f;
            S[f][2] = k0 ? S[f][2] * 0.125f : -1.0e9f;
            S[f][3] = k1 ? S[f][3] * 0.125f : -1.0e9f;
            mx0 = fmaxf(mx0, fmaxf(S[f][0], S[f][1]));
            mx1 = fmaxf(mx1, fmaxf(S[f][2], S[f][3]));
        }
        #pragma unroll
        for (int o = 1; o < 4; o <<= 1) {
            mx0 = fmaxf(mx0, __shfl_xor_sync(0xffffffffu, mx0, o));
            mx1 = fmaxf(mx1, __shfl_xor_sync(0xffffffffu, mx1, o));
        }
        const float sc0 = expf(mrow0 - mx0);
        const float sc1 = expf(mrow1 - mx1);
        mrow0 = mx0; mrow1 = mx1;
        lrow0 *= sc0; lrow1 *= sc1;
        #pragma unroll
        for (int f = 0; f < 8; f++) {
            O[f][0] *= sc0; O[f][1] *= sc0; O[f][2] *= sc1; O[f][3] *= sc1;
        }
        uint32_t P[8][4];
        float rs0 = 0.f, rs1 = 0.f;
        #pragma unroll
        for (int nf2 = 0; nf2 < 8; nf2++) {
            float p00 = expf(S[2 * nf2][0] - mx0),     p01 = expf(S[2 * nf2][1] - mx0);
            float p10 = expf(S[2 * nf2][2] - mx1),     p11 = expf(S[2 * nf2][3] - mx1);
            float p20 = expf(S[2 * nf2 + 1][0] - mx0), p21 = expf(S[2 * nf2 + 1][1] - mx0);
            float p30 = expf(S[2 * nf2 + 1][2] - mx1), p31 = expf(S[2 * nf2 + 1][3] - mx1);
            rs0 += p00 + p01 + p20 + p21;
            rs1 += p10 + p11 + p30 + p31;
            P[nf2][0] = packf2(p00, p01);
            P[nf2][1] = packf2(p10, p11);
            P[nf2][2] = packf2(p20, p21);
            P[nf2][3] = packf2(p30, p31);
        }
        #pragma unroll
        for (int o = 1; o < 4; o <<= 1) {
            rs0 += __shfl_xor_sync(0xffffffffu, rs0, o);
            rs1 += __shfl_xor_sync(0xffffffffu, rs1, o);
        }
        lrow0 += rs0; lrow1 += rs1;

        #pragma unroll
        for (int ks2 = 0; ks2 < 8; ks2++) {
            #pragma unroll
            for (int dn = 0; dn < 4; dn++) {
                uint32_t th[4], tl[4];
                ldsm4(th, sb + V0 + (uint32_t)((bRow + dn * 16) * VROWB + (ks2 * 16 + bKs) * 2));
                ldsm4(tl, sb + V0 + VPLB + (uint32_t)((bRow + dn * 16) * VROWB + (ks2 * 16 + bKs) * 2));
                uint32_t bh0[2] = {th[0], th[1]}, bh1[2] = {th[2], th[3]};
                uint32_t bl0[2] = {tl[0], tl[1]}, bl1[2] = {tl[2], tl[3]};
                mma16816(O[2 * dn],     P[ks2], bh0);
                mma16816(O[2 * dn + 1], P[ks2], bh1);
                mma16816(O[2 * dn],     P[ks2], bl0);
                mma16816(O[2 * dn + 1], P[ks2], bl1);
            }
        }
        __syncthreads();
    }

    const float li0 = 1.f / lrow0, li1 = 1.f / lrow1;
    const int row0 = m0 + wid * 16 + (lane >> 2);
    __nv_bfloat16* ob = o2 + (size_t)b * ND;
    #pragma unroll
    for (int f = 0; f < 8; f++) {
        int d = hc * DH + f * 8 + q2c;
        float v00 = O[f][0] * li0, v01 = O[f][1] * li0;
        float v10 = O[f][2] * li1, v11 = O[f][3] * li1;
        __nv_bfloat16 h00, l00, h01, l01, h10, l10, h11, l11;
        split1(v00, h00, l00); split1(v01, h01, l01);
        split1(v10, h10, l10); split1(v11, h11, l11);
        size_t o0 = (size_t)row0 * Dd + d;
        size_t o1 = (size_t)(row0 + 8) * Dd + d;
        *reinterpret_cast<uint32_t*>(ob + o0) = pack2(h00, h01);
        *reinterpret_cast<uint32_t*>(ob + o1) = pack2(h10, h11);
        *reinterpret_cast<uint32_t*>(ob + plane + o0) = pack2(l00, l01);
        *reinterpret_cast<uint32_t*>(ob + plane + o1) = pack2(l10, l11);
    }
}

// ---------------- auxiliary kernels ----------------
__global__ void k_posquery1(const float* __restrict__ x, const int* __restrict__ mask,
                            float* __restrict__ part, float* __restrict__ cntp)
{
    int seg = blockIdx.x, b = blockIdx.y, d = threadIdx.x;
    int n0 = seg * 64;
    float s = 0.f, cnt = 0.f;
    for (int n = n0; n < n0 + 64; n++) {
        if (mask[b * Nn + n] == 1) { s += x[((size_t)b * Nn + n) * Dd + d]; cnt += 1.f; }
    }
    part[((size_t)b * 16 + seg) * Dd + d] = s;
    if (d == 0) cntp[b * 16 + seg] = cnt;
}
__global__ void k_posquery2(const float* __restrict__ part, const float* __restrict__ cntp,
                            float* __restrict__ pq)
{
    int b = blockIdx.x, d = threadIdx.x;
    float s = 0.f, cnt = 0.f;
    #pragma unroll
    for (int seg = 0; seg < 16; seg++) {
        s += part[((size_t)b * 16 + seg) * Dd + d];
        cnt += cntp[b * 16 + seg];
    }
    pq[b * Dd + d] = s / fmaxf(cnt, 1.f);
}

__global__ void k_mv1(const float* __restrict__ Wq, const float* __restrict__ pq,
                      float* __restrict__ qs)
{
    __shared__ float spq[Dd];
    __shared__ float red[8][32];
    int b = blockIdx.y, t0 = blockIdx.x * 32;
    int tid = threadIdx.x;
    spq[tid] = pq[b * Dd + tid];
    __syncthreads();
    int tseg = tid >> 5, tl = tid & 31;
    float s = 0.f;
    #pragma unroll
    for (int i = 0; i < 32; i++)
        s += spq[tseg * 32 + i] * Wq[(tseg * 32 + i) * Dd + t0 + tl];
    red[tseg][tl] = s;
    __syncthreads();
    if (tseg == 0) {
        float a = 0.f;
        #pragma unroll
        for (int k = 0; k < 8; k++) a += red[k][tl];
        qs[b * Dd + t0 + tl] = a;
    }
}
__global__ void k_mv2(const float* __restrict__ Wx, const float* __restrict__ qs,
                      float* __restrict__ w)
{
    int b = blockIdx.y;
    int wid = threadIdx.x >> 5, lane = threadIdx.x & 31;
    int t = blockIdx.x * 8 + wid;
    float s = 0.f;
    #pragma unroll
    for (int k = 0; k < 8; k++)
        s += Wx[(size_t)t * Dd + lane + 32 * k] * qs[b * Dd + lane + 32 * k];
    #pragma unroll
    for (int o = 16; o; o >>= 1) s += __shfl_xor_sync(0xffffffffu, s, o);
    if (lane == 0) w[b * Dd + t] = s;
}

__global__ void k_possim(const float* __restrict__ x, const float* __restrict__ w,
                         float* __restrict__ possim_out, float* __restrict__ sel)
{
    int row = blockIdx.x * 8 + (threadIdx.x >> 5);
    int lane = threadIdx.x & 31;
    int b = row / Nn;
    const float4* xr = reinterpret_cast<const float4*>(x + (size_t)row * Dd);
    const float4* wr = reinterpret_cast<const float4*>(w + b * Dd);
    float s = 0.f;
    #pragma unroll
    for (int e = 0; e < 2; e++) {
        float4 xv = xr[lane + e * 32];
        float4 wv = wr[lane + e * 32];
        s += xv.x * wv.x + xv.y * wv.y + xv.z * wv.z + xv.w * wv.w;
    }
    #pragma unroll
    for (int o = 16; o; o >>= 1) s += __shfl_xor_sync(0xffffffffu, s, o);
    if (lane == 0) {
        float p = 1.f / (1.f + expf(-s * 0.0625f));
        possim_out[row] = p;
        sel[row] = (p > 0.97f) ? 1.f : 0.f;
    }
}

__global__ void k_softmax_gat(const float* __restrict__ s1, const float* __restrict__ s2,
                              const uint8_t* __restrict__ connect, __nv_bfloat16* __restrict__ attn,
                              int nheads)
{
    __shared__ float s2row[Nn];
    __shared__ float r8[8];
    int z = blockIdx.y;
    int b = z / nheads;
    int t = threadIdx.x;
    int wid = t >> 5, lane = t & 31;
    #pragma unroll
    for (int k = 0; k < 4; k++) s2row[t + k * 256] = s2[(size_t)z * Nn + t + k * 256];
    __syncthreads();
    #pragma unroll
    for (int r = 0; r < 4; r++) {
        int i = blockIdx.x * 4 + r;
        const uint8_t* con = connect + (size_t)b * NNt + (size_t)i * Nn;
        float s1v = s1[(size_t)z * Nn + i];
        float v[4];
        float mx = -INFINITY;
        #pragma unroll
        for (int k = 0; k < 4; k++) {
            int j = t + k * 256;
            float e = s1v + s2row[j];
            e = (e >= 0.f) ? e : 0.2f * e;
            v[k] = con[j] ? e : -9.0e15f;
            mx = fmaxf(mx, v[k]);
        }
        mx = bred<true>(mx, r8, wid, lane);
        float sum = 0.f;
        #pragma unroll
        for (int k = 0; k < 4; k++) { v[k] = expf(v[k] - mx); sum += v[k]; }
        sum = bred<false>(sum, r8, wid, lane);
        float inv = 1.f / sum;
        __nv_bfloat16* out = attn + (size_t)z * NNt + (size_t)i * Nn;
        #pragma unroll
        for (int k = 0; k < 4; k++) out[t + k * 256] = __float2bfloat16(v[k] * inv);
        __syncthreads();
    }
}

__global__ void k_ln(const float* __restrict__ in, const float* __restrict__ g,
                     const float* __restrict__ bb, __nv_bfloat16* __restrict__ out, long oplane)
{
    int row = blockIdx.x * 8 + (threadIdx.x >> 5);
    int lane = threadIdx.x & 31;
    size_t base = (size_t)row * Dd;
    float vbuf[8];
    float s = 0.f, sq = 0.f;
    #pragma unroll
    for (int k = 0; k < 8; k++) {
        float x = in[base + lane + k * 32];
        vbuf[k] = x; s += x; sq += x * x;
    }
    #pragma unroll
    for (int o = 16; o; o >>= 1) {
        s += __shfl_xor_sync(0xffffffffu, s, o);
        sq += __shfl_xor_sync(0xffffffffu, sq, o);
    }
    float mean = s * (1.f / Dd);
    float var = sq * (1.f / Dd) - mean * mean;
    float rstd = rsqrtf(var + 1e-5f);
    #pragma unroll
    for (int k = 0; k < 8; k++) {
        int d = lane + k * 32;
        float y = (vbuf[k] - mean) * rstd * g[d] + bb[d];
        __nv_bfloat16 h, l; split1(y, h, l);
        out[base + d] = h; out[oplane + base + d] = l;
    }
}

__global__ void k_qfull_ln(const __nv_bfloat16* __restrict__ gout, long gplane,
                           const float* __restrict__ pe,
                           const float* __restrict__ sel, const float* __restrict__ g,
                           const float* __restrict__ bb, __nv_bfloat16* __restrict__ out, long oplane)
{
    int row = blockIdx.x * 8 + (threadIdx.x >> 5);
    int lane = threadIdx.x & 31;
    int n = row % Nn;
    size_t base = (size_t)row * Dd;
    float selv = sel[row];
    float vbuf[8];
    float s = 0.f, sq = 0.f;
    #pragma unroll
    for (int k = 0; k < 8; k++) {
        int d = lane + k * 32;
        float gv = __bfloat162float(gout[base + d]) + __bfloat162float(gout[gplane + base + d]);
        float x = (selv > 0.5f) ? (gv + pe[(size_t)n * Dd + d]) : 0.f;
        vbuf[k] = x; s += x; sq += x * x;
    }
    #pragma unroll
    for (int o = 16; o; o >>= 1) {
        s += __shfl_xor_sync(0xffffffffu, s, o);
        sq += __shfl_xor_sync(0xffffffffu, sq, o);
    }
    float mean = s * (1.f / Dd);
    float var = sq * (1.f / Dd) - mean * mean;
    float rstd = rsqrtf(var + 1e-5f);
    #pragma unroll
    for (int k = 0; k < 8; k++) {
        int d = lane + k * 32;
        float y = (vbuf[k] - mean) * rstd * g[d] + bb[d];
        __nv_bfloat16 h, l; split1(y, h, l);
        out[base + d] = h; out[oplane + base + d] = l;
    }
}

// ---------------- launch ----------------
#define GETSYM(p, T, s) do { void* _t; cudaGetSymbolAddress(&_t, s); p = (T*)_t; } while (0)
#define SMEMSZ(BM, BN, NA, NB) ((2 * (NA) * (BM) + 2 * (NB) * (BN)) * ROWB)

extern "C" void kernel_launch(void* const* d_in, const int* in_sizes, int n_in,
                              void* d_out, int out_size)
{
    const float* x      = (const float*)d_in[0];
    const int*   mask   = (const int*)  d_in[1];
    const float* pe     = (const float*)d_in[2];
    const float* simWx  = (const float*)d_in[3];
    const float* simWq  = (const float*)d_in[4];
    const float* adjW   = (const float*)d_in[5];
    const float* gatW   = (const float*)d_in[6];
    const float* gatA1  = (const float*)d_in[7];
    const float* gatA2  = (const float*)d_in[8];
    const float* gatWo  = (const float*)d_in[9];
    const float* gatAo1 = (const float*)d_in[10];
    const float* gatAo2 = (const float*)d_in[11];
    const float* ln3g   = (const float*)d_in[12];
    const float* ln3b   = (const float*)d_in[13];
    const float* ln4g   = (const float*)d_in[14];
    const float* ln4b   = (const float*)d_in[15];
    const float* caWq   = (const float*)d_in[16];
    const float* caWk   = (const float*)d_in[17];
    const float* caWv   = (const float*)d_in[18];
    const float* caWp   = (const float*)d_in[19];
    const float* gamma  = (const float*)d_in[20];
    (void)in_sizes; (void)n_in; (void)out_size;

    float* out = (float*)d_out;
    float* possim_out = out + (size_t)Bz * Nn * Dd;

    float *posq, *pqpart, *pqcnt, *qsv, *w, *sel, *s1, *s2, *so1, *so2;
    uint8_t* connect;
    __nv_bfloat16 *attn_bf, *attno_bf;
    __nv_bfloat16 *x2, *fa2, *WhT2, *cat2, *WhoT2, *gout2, *qx2, *kv2;
    __nv_bfloat16 *q2, *k2, *vT2, *o2;
    __nv_bfloat16 *adjWT2, *gatWT2, *WoT2, *caWqT2, *caWkT2, *caWvT2, *caWpT2;
    GETSYM(posq, float, g_posq);   GETSYM(pqpart, float, g_pqpart); GETSYM(pqcnt, float, g_pqcnt);
    GETSYM(qsv, float, g_qs);      GETSYM(w, float, g_w);       GETSYM(sel, float, g_sel);
    GETSYM(connect, uint8_t, g_connect);
    GETSYM(s1, float, g_s1);       GETSYM(s2, float, g_s2);
    GETSYM(so1, float, g_so1);     GETSYM(so2, float, g_so2);
    GETSYM(attn_bf, __nv_bfloat16, g_attn_bf);
    GETSYM(attno_bf, __nv_bfloat16, g_attno_bf);
    GETSYM(x2, __nv_bfloat16, g_x2);     GETSYM(fa2, __nv_bfloat16, g_fa2);
    GETSYM(WhT2, __nv_bfloat16, g_WhT2);
    GETSYM(cat2, __nv_bfloat16, g_cat2);
    GETSYM(WhoT2, __nv_bfloat16, g_WhoT2);
    GETSYM(gout2, __nv_bfloat16, g_gout2);
    GETSYM(qx2, __nv_bfloat16, g_qx2);   GETSYM(kv2, __nv_bfloat16, g_kv2);
    GETSYM(q2, __nv_bfloat16, g_q2);     GETSYM(k2, __nv_bfloat16, g_k2);
    GETSYM(vT2, __nv_bfloat16, g_vT2);   GETSYM(o2, __nv_bfloat16, g_o2);
    GETSYM(adjWT2, __nv_bfloat16, g_adjWT2); GETSYM(gatWT2, __nv_bfloat16, g_gatWT2);
    GETSYM(WoT2, __nv_bfloat16, g_WoT2);
    GETSYM(caWqT2, __nv_bfloat16, g_caWqT2); GETSYM(caWkT2, __nv_bfloat16, g_caWkT2);
    GETSYM(caWvT2, __nv_bfloat16, g_caWvT2); GETSYM(caWpT2, __nv_bfloat16, g_caWpT2);

    const long PL_BND  = (long)Bz * ND;
    const long PL_BHND = (long)Bz * Hh * ND;
    const long PL_CAT  = (long)Bz * Nn * HD;
    const long PL_DD   = (long)Dd * Dd;
    const long PL_GATW = (long)Hh * Dd * Dd;
    const long PL_WO   = (long)HD * Dd;
    const long PL_S    = (long)Bz * Hh * Nn;   // s1->s2 offset
    const long PL_SO   = (long)Bz * Nn;        // so1->so2 offset

    const int SM_M2_22 = SMEMSZ(64, 128, 2, 2);
    const int SM_M2_12 = SMEMSZ(64, 128, 1, 2);
    const int SM_M4_22 = SMEMSZ(128, 128, 2, 2);
    const int SM_M4_11 = SMEMSZ(128, 128, 1, 1);
    cudaFuncSetAttribute(mma_gemm<2,128,2,4,EPI_NONE,   2,2,OUT_PLANES, false,true,0>, cudaFuncAttributeMaxDynamicSharedMemorySize, SM_M2_22);
    cudaFuncSetAttribute(mma_gemm<2,128,2,4,EPI_NONE,   2,2,OUT_NONE,   true ,true,1>, cudaFuncAttributeMaxDynamicSharedMemorySize, SM_M2_22);
    cudaFuncSetAttribute(mma_gemm<2,128,2,4,EPI_NONE,   2,2,OUT_NONE,   true ,true,0>, cudaFuncAttributeMaxDynamicSharedMemorySize, SM_M2_22);
    cudaFuncSetAttribute(mma_gemm<2,128,2,4,EPI_RESID,  2,2,OUT_F32,    false,true,0>, cudaFuncAttributeMaxDynamicSharedMemorySize, SM_M2_22);
    cudaFuncSetAttribute(mma_gemm<2,128,2,4,EPI_ELU,    1,2,OUT_PLANES, false,true,0>, cudaFuncAttributeMaxDynamicSharedMemorySize, SM_M2_12);
    cudaFuncSetAttribute(mma_gemm<4,128,2,4,EPI_NONE,   2,2,OUT_NONE,   true ,false,1>, cudaFuncAttributeMaxDynamicSharedMemorySize, SM_M4_22);
    cudaFuncSetAttribute(mma_gemm<4,128,2,4,EPI_CONNECT,2,2,OUT_CONNECT,false,true,0>, cudaFuncAttributeMaxDynamicSharedMemorySize, SM_M4_22);
    cudaFuncSetAttribute(mma_gemm<4,128,2,4,EPI_ELU,    1,1,OUT_PLANES, false,true,0>, cudaFuncAttributeMaxDynamicSharedMemorySize, SM_M4_11);
    cudaFuncSetAttribute(k_flash_ca, cudaFuncAttributeMaxDynamicSharedMemorySize, FCA_SMEM);

    const long zero = 0;
    cudaStream_t s0 = 0;
    cudaStream_t sA = hx.s1;
    cudaStream_t sB = hx.s2;

    // fork
    cudaEventRecord(hx.e0, s0);
    cudaStreamWaitEvent(sA, hx.e0, 0);
    cudaStreamWaitEvent(sB, hx.e0, 0);

    // zero dot accumulators (tiny; before producing GEMMs)
    cudaMemsetAsync(s1, 0, (size_t)Bz * Hh * Nn * 4, s0);
    cudaMemsetAsync(s2, 0, (size_t)Bz * Hh * Nn * 4, s0);
    cudaMemsetAsync(so1, 0, (size_t)Bz * Nn * 4, s0);
    cudaMemsetAsync(so2, 0, (size_t)Bz * Nn * 4, s0);

    // stream B: weight transposes -> LN3 -> q projection
    k_transpose_all<<<1344, dim3(32, 8), 0, sB>>>(adjW, adjWT2, caWq, caWqT2, caWk, caWkT2,
                                                  caWv, caWvT2, caWp, caWpT2, gatW, gatWT2, gatWo, WoT2);
    cudaEventRecord(hx.eT, sB);
    k_ln<<<Bz * Nn / 8, 256, 0, sB>>>(x, ln3g, ln3b, qx2, PL_BND);

    // stream 0: split x
    k_split<<<Bz * ND / 1024, 256, 0, s0>>>(x, x2, PL_BND);
    cudaEventRecord(hx.eX, s0);

    // stream B: q = qx @ caWq
    mma_gemm<2,128,2,4,EPI_NONE,2,2,OUT_PLANES,false,true,0><<<dim3(2, 128, 1), 256, SM_M2_22, sB>>>(
        qx2, PL_BND, caWqT2, PL_DD, q2, PL_BND,
        Dd, Dd, Dd, Dd, 1, zero, zero, zero, zero, zero, zero,
        nullptr, zero, nullptr, nullptr, zero, zero, zero, 0);
    cudaEventRecord(hx.eQ, sB);

    // stream A: selection path, then fa -> connect (full precision)
    k_posquery1<<<dim3(16, Bz), 256, 0, sA>>>(x, mask, pqpart, pqcnt);
    k_posquery2<<<Bz, 256, 0, sA>>>(pqpart, pqcnt, posq);
    k_mv1<<<dim3(8, Bz), 256, 0, sA>>>(simWq, posq, qsv);
    k_mv2<<<dim3(32, Bz), 256, 0, sA>>>(simWx, qsv, w);
    k_possim<<<Bz * Nn / 8, 256, 0, sA>>>(x, w, possim_out, sel);
    cudaStreamWaitEvent(sA, hx.eX, 0);
    cudaStreamWaitEvent(sA, hx.eT, 0);
    mma_gemm<2,128,2,4,EPI_NONE,2,2,OUT_PLANES,false,true,0><<<dim3(2, 128, 1), 256, SM_M2_22, sA>>>(
        x2, PL_BND, adjWT2, PL_DD, fa2, PL_BND,
        Dd, Dd, Dd, Dd, 1, zero, zero, zero, zero, zero, zero,
        nullptr, zero, nullptr, nullptr, zero, zero, zero, 0);
    mma_gemm<4,128,2,4,EPI_CONNECT,2,2,OUT_CONNECT,false,true,0><<<dim3(8, 8, Bz), 256, SM_M4_22, sA>>>(
        fa2, PL_BND, fa2, PL_BND, connect, zero,
        Dd, Dd, Dd, Nn, 1, (long)ND, zero, (long)ND, zero, (long)NNt, zero,
        sel, (long)Nn, nullptr, nullptr, zero, zero, zero, 0);
    cudaEventRecord(hx.eConn, sA);

    // stream 0: main chain
    cudaStreamWaitEvent(s0, hx.eT, 0);

    // Wh GEMM: no Wh planes written; WhT hi-only; fused a1/a2 dots into s1/s2
    mma_gemm<4,128,2,4,EPI_NONE,2,2,OUT_NONE,true,false,1><<<dim3(2, 8, Bz * Hh), 256, SM_M4_22, s0>>>(
        x2, PL_BND, gatWT2, PL_GATW, s1, PL_S,
        Dd, Dd, Dd, Dd, Hh, (long)ND, zero, zero, (long)Dd * Dd, zero, zero,
        gatA1, (long)Dd, gatA2, WhT2, PL_BHND, (long)Hh * ND, (long)ND, Nn);

    cudaStreamWaitEvent(s0, hx.eConn, 0);
    k_softmax_gat<<<dim3(Nn / 4, Bz * Hh), 256, 0, s0>>>(s1, s2, connect, attn_bf, Hh);

    // cat = elu( attn @ Wh )  [1 product: P_hi x Wh_hi]
    mma_gemm<4,128,2,4,EPI_ELU,1,1,OUT_PLANES,false,true,0><<<dim3(2, 8, Bz * Hh), 256, SM_M4_11, s0>>>(
        attn_bf, zero, WhT2, PL_BHND, cat2, PL_CAT,
        Nn, Nn, Nn, HD, Hh, (long)Hh * NNt, (long)NNt, (long)Hh * ND, (long)ND,
        (long)Nn * HD, (long)Dd,
        nullptr, zero, nullptr, nullptr, zero, zero, zero, 0);

    // Who GEMM: 3-product; no Who planes; WhoT both planes; fused ao dots into so1/so2
    mma_gemm<2,128,2,4,EPI_NONE,2,2,OUT_NONE,true,true,1><<<dim3(2, 16, Bz), 256, SM_M2_22, s0>>>(
        cat2, PL_CAT, WoT2, PL_WO, so1, PL_SO,
        HD, HD, HD, Dd, 1, (long)Nn * HD, zero, zero, zero, (long)Nn, zero,
        gatAo1, zero, gatAo2, WhoT2, PL_BND, (long)ND, zero, Nn);

    k_softmax_gat<<<dim3(Nn / 4, Bz), 256, 0, s0>>>(so1, so2, connect, attno_bf, 1);

    // gout = elu( attn_o @ Who )  [2 products]
    mma_gemm<2,128,2,4,EPI_ELU,1,2,OUT_PLANES,false,true,0><<<dim3(2, 16, Bz), 256, SM_M2_12, s0>>>(
        attno_bf, zero, WhoT2, PL_BND, gout2, PL_BND,
        Nn, Nn, Nn, Dd, 1, (long)NNt, zero, (long)ND, zero, (long)ND, zero,
        nullptr, zero, nullptr, nullptr, zero, zero, zero, 0);

    k_qfull_ln<<<Bz * Nn / 8, 256, 0, s0>>>(gout2, PL_BND, pe, sel, ln4g, ln4b, kv2, PL_BND);
    cudaEventRecord(hx.eKV, s0);

    // stream B: k projection (parallel with vT on s0)
    cudaStreamWaitEvent(sB, hx.eKV, 0);
    mma_gemm<2,128,2,4,EPI_NONE,2,2,OUT_PLANES,false,true,0><<<dim3(2, 128, 1), 256, SM_M2_22, sB>>>(
        kv2, PL_BND, caWkT2, PL_DD, k2, PL_BND,
        Dd, Dd, Dd, Dd, 1, zero, zero, zero, zero, zero, zero,
        nullptr, zero, nullptr, nullptr, zero, zero, zero, 0);
    cudaEventRecord(hx.eK, sB);

    // stream 0: v projection (transposed planes only)
    mma_gemm<2,128,2,4,EPI_NONE,2,2,OUT_NONE,true,true,0><<<dim3(2, 16, Bz), 256, SM_M2_22, s0>>>(
        kv2, PL_BND, caWvT2, PL_DD, nullptr, zero,
        Dd, Dd, Dd, Dd, 1, (long)ND, zero, zero, zero, (long)ND, zero,
        nullptr, zero, nullptr, vT2, PL_BND, (long)ND, zero, Nn);

    // fused flash CA
    cudaStreamWaitEvent(s0, hx.eQ, 0);
    cudaStreamWaitEvent(s0, hx.eK, 0);
    k_flash_ca<<<dim3(Nn / 128, Bz * HC), 256, FCA_SMEM, s0>>>(
        q2, k2, vT2, sel, o2, PL_BND);

    // out = x + gamma * (o @ caWp)
    mma_gemm<2,128,2,4,EPI_RESID,2,2,OUT_F32,false,true,0><<<dim3(2, 128, 1), 256, SM_M2_22, s0>>>(
        o2, PL_BND, caWpT2, PL_DD, out, zero,
        Dd, Dd, Dd, Dd, 1, zero, zero, zero, zero, zero, zero,
        x, zero, gamma, nullptr, zero, zero, zero, 0);
}